// round 7
// baseline (speedup 1.0000x reference)
#include <cuda_runtime.h>
#include <cuda_fp16.h>
#include <stdint.h>
#include <math.h>

#define BB   64
#define TT   512
#define IND  256
#define OUTD 256
#define HH   1024
#define NCTA 64
#define KB   128          // fp16 elements per K-chunk
#define KP16 144          // smem row stride (halfs) = 288B, conflict-free LDS.64
#define NST  3            // pipeline stages

// ---------------- persistent device state ----------------
__device__ __half   g_h0p[2][BB * HH];
__device__ __half   g_h1p[2][BB * HH];
__device__ __half   g_h1all[(long)TT * BB * HH];
__device__ __half   g_xp[(long)TT * BB * IND];
__device__ __half   g_W1i[NCTA * 64 * HH];
__device__ __half   g_W0h[NCTA * 64 * HH];
__device__ __half   g_W1h[NCTA * 64 * HH];
__device__ __half   g_W0x[NCTA * 64 * IND];
__device__ __half   g_Wlp[(OUTD / 64) * 64 * HH];
__device__ unsigned g_cnt[256];                 // 8 counters, one per 128B line

// ---------------- helpers ----------------
__device__ __forceinline__ float sigm(float v) { return 1.f / (1.f + __expf(-v)); }

// k-permutation within each 16-group: lane quad (2q,2q+1,2q+8,2q+9) contiguous.
__device__ __forceinline__ int kpos16(int k) {
    int q = k >> 1, b = k & 1;
    return ((q & 3) << 2) | ((q >> 2) << 1) | b;
}
__device__ __forceinline__ int kinv16(int p) {
    int b = p & 1, hi = (p >> 1) & 1, mid = (p >> 2) & 3;
    return 2 * (mid | (hi << 2)) + b;
}

__device__ __forceinline__ void cp_async16(void* dst, const void* src) {
    uint32_t d = (uint32_t)__cvta_generic_to_shared(dst);
    asm volatile("cp.async.cg.shared.global [%0], [%1], 16;\n" :: "r"(d), "l"(src));
}
#define CP_COMMIT() asm volatile("cp.async.commit_group;\n" ::: "memory")
#define CP_WAIT(N)  asm volatile("cp.async.wait_group %0;\n" :: "n"(N) : "memory")

__device__ __forceinline__ unsigned ld_acq(const unsigned* p) {
    unsigned v;
    asm volatile("ld.acquire.gpu.global.u32 %0, [%1];" : "=r"(v) : "l"(p) : "memory");
    return v;
}

// Distributed-counter grid barrier: CTA b arrives on counter b&7 (separate L2
// lines -> 8x less atomic serialization); waiter sums all 8 with acquire loads.
__device__ __forceinline__ void grid_bar(unsigned target) {
    __syncthreads();
    if (threadIdx.x == 0) {
        __threadfence();
        atomicAdd(&g_cnt[(blockIdx.x & 7) << 5], 1u);
        unsigned s;
        do {
            s = 0;
#pragma unroll
            for (int i = 0; i < 8; i++) s += ld_acq(&g_cnt[i << 5]);
        } while (s < target);
    }
    __syncthreads();
}

__device__ __forceinline__ void hmma(float* c, uint32_t a0, uint32_t a1, uint32_t a2,
                                     uint32_t a3, uint32_t b0, uint32_t b1) {
    asm volatile(
        "mma.sync.aligned.m16n8k16.row.col.f32.f16.f16.f32 "
        "{%0,%1,%2,%3}, {%4,%5,%6,%7}, {%8,%9}, {%0,%1,%2,%3};"
        : "+f"(c[0]), "+f"(c[1]), "+f"(c[2]), "+f"(c[3])
        : "r"(a0), "r"(a1), "r"(a2), "r"(a3), "r"(b0), "r"(b1));
}

// Fill one 64-row x 128-half tile via cp.async (4 x 16B per thread).
__device__ __forceinline__ void fill64(__half (*S)[KP16], const __half* __restrict__ src,
                                       int ld, int tid) {
#pragma unroll
    for (int it = 0; it < 4; it++) {
        int idx = tid + it * 256;
        int row = idx >> 4;
        int seg = (idx & 15) << 3;
        cp_async16(&S[row][seg], src + (long)row * ld + seg);
    }
}

// Warp computes m32 x n32 over its K-half (4 kgroups) of one chunk.
__device__ __forceinline__ void mma64(const __half (*A)[KP16], const __half (*B)[KP16],
                                      float (*acc)[8], int mrow, int ncol, int kbase,
                                      int l4, int lq) {
#pragma unroll
    for (int g = 0; g < 4; g++) {
        int off = kbase + g * 16 + 4 * lq;
        uint2 a0 = *(const uint2*)&A[mrow + l4][off];
        uint2 a1 = *(const uint2*)&A[mrow + 8 + l4][off];
        uint2 a2 = *(const uint2*)&A[mrow + 16 + l4][off];
        uint2 a3 = *(const uint2*)&A[mrow + 24 + l4][off];
#pragma unroll
        for (int nt = 0; nt < 4; nt++) {
            uint2 b = *(const uint2*)&B[ncol + nt * 8 + l4][off];
            hmma(&acc[nt][0], a0.x, a1.x, a0.y, a1.y, b.x, b.y);
            hmma(&acc[nt][4], a2.x, a3.x, a2.y, a3.y, b.x, b.y);
        }
    }
}

// Gate gather: ks=0 warps write, ks=1 warps add (K-split reduction via smem).
__device__ __forceinline__ void gather(float (*gs)[72], float (*acc)[8],
                                       int mrow, int ncol, int l4, int lq, bool add) {
#pragma unroll
    for (int nt = 0; nt < 4; nt++) {
        int c = ncol + nt * 8 + 2 * lq;
#pragma unroll
        for (int mh = 0; mh < 4; mh++) {
            int r = mrow + mh * 8 + l4;
            float v0 = acc[nt][mh * 2], v1 = acc[nt][mh * 2 + 1];
            if (add) {
                float2 o = *(float2*)&gs[r][c];
                o.x += v0; o.y += v1;
                *(float2*)&gs[r][c] = o;
            } else {
                *(float2*)&gs[r][c] = make_float2(v0, v1);
            }
        }
    }
}

// LSTM cell over the CTA's 16 dims x 64 rows.
__device__ __forceinline__ void cell_pass(const float (*gs)[72], const float* bs,
                                          float (*cc)[16], __half* dst, __half* hist,
                                          int d0, int tid) {
#pragma unroll
    for (int s = 0; s < 4; s++) {
        int idx = tid + s * 256;
        int r = idx >> 4, j = idx & 15;
        float gi = gs[r][j]      + bs[j];
        float gf = gs[r][16 + j] + bs[16 + j];
        float gg = gs[r][32 + j] + bs[32 + j];
        float go = gs[r][48 + j] + bs[48 + j];
        float c = sigm(gf) * cc[r][j] + sigm(gi) * tanhf(gg);
        cc[r][j] = c;
        __half h = __float2half_rn(sigm(go) * tanhf(c));
        long off = (long)r * HH + d0 + kpos16(j);
        dst[off] = h;
        if (hist) hist[off] = h;
    }
}

// ---------------- init / pack kernels ----------------
__global__ void init_kernel(const float* __restrict__ z) {
    int i = blockIdx.x * blockDim.x + threadIdx.x;     // over BB*HH
    int k = i & (HH - 1);
    long pk = (long)(i & ~(HH - 1)) + (k & ~15) + kpos16(k & 15);
    __half v = __float2half_rn(z[i]);
    g_h0p[0][pk] = v;
    g_h1p[0][pk] = v;
    if (i < 256) g_cnt[i] = 0u;
}

// dst[blk][c][kp] <- src[(c>>4)*1024 + blk*16 + (c&15)][k],  c = 0..63
__global__ void pack_w(const float* __restrict__ src, __half* __restrict__ dst,
                       int K, int total) {
    for (int i = blockIdx.x * blockDim.x + threadIdx.x; i < total;
         i += gridDim.x * blockDim.x) {
        int kp = i % K;
        int c  = (i / K) & 63;
        int blk = i / (K * 64);
        int k = (kp & ~15) + kinv16(kp & 15);
        int row = ((c >> 4) << 10) + (blk << 4) + (c & 15);
        dst[i] = __float2half_rn(src[(long)row * K + k]);
    }
}

// dst[blk][c][kp] <- src[blk*64+c][k]
__global__ void pack_wl(const float* __restrict__ src, __half* __restrict__ dst,
                        int K, int total) {
    for (int i = blockIdx.x * blockDim.x + threadIdx.x; i < total;
         i += gridDim.x * blockDim.x) {
        int kp = i % K;
        int c  = (i / K) & 63;
        int blk = i / (K * 64);
        int k = (kp & ~15) + kinv16(kp & 15);
        dst[i] = __float2half_rn(src[(long)(blk * 64 + c) * K + k]);
    }
}

__global__ void pack_x(const float* __restrict__ x) {
    long total = (long)TT * BB * IND;
    for (long i = blockIdx.x * (long)blockDim.x + threadIdx.x; i < total;
         i += (long)gridDim.x * blockDim.x) {
        int kp = (int)(i % IND);
        int b  = (int)((i / IND) & 63);
        int t  = (int)(i / (IND * 64));
        int k = (kp & ~15) + kinv16(kp & 15);
        g_xp[i] = __float2half_rn(x[((long)b * TT + t) * IND + k]);
    }
}

// ---------------- main persistent kernel ----------------
__global__ __launch_bounds__(256) void lstm_persist(
    const float* __restrict__ bih0, const float* __restrict__ bhh0,
    const float* __restrict__ bih1, const float* __restrict__ bhh1)
{
    extern __shared__ __align__(16) unsigned char smraw[];
    __half (*SM)[KP16] = (__half(*)[KP16])smraw;          // NST*192 rows
    float* fext  = (float*)(smraw + NST * 192 * KP16 * 2);
    float* bsum0 = fext;
    float* bsum1 = fext + 64;
    float (*cc0)[16] = (float(*)[16])(fext + 128);        // 64 x 16
    float (*cc1)[16] = cc0 + 64;
    float (*gsB)[72] = (float(*)[72])smraw;               // aliases stage area
    float (*gsA)[72] = gsB + 64;

    int tid = threadIdx.x, lane = tid & 31, w = tid >> 5;
    int ks = w >> 2, my = (w >> 1) & 1, nx = w & 1;
    int mrow = my * 32, ncol = nx * 32, kbase = ks * 64;
    int l4 = lane >> 2, lq = lane & 3;
    int blk = blockIdx.x, d0 = blk * 16;

    const __half* W1i = g_W1i + (long)blk * 64 * HH;
    const __half* W0h = g_W0h + (long)blk * 64 * HH;
    const __half* W1h = g_W1h + (long)blk * 64 * HH;
    const __half* W0x = g_W0x + (long)blk * 64 * IND;

    if (tid < 64) {
        int g = tid >> 4, j = tid & 15, n = (g << 10) + d0 + j;
        bsum0[tid] = bih0[n] + bhh0[n];
        bsum1[tid] = bih1[n] + bhh1[n];
    }
#pragma unroll
    for (int s = 0; s < 8; s++) ((float*)cc0)[tid + s * 256] = 0.f;  // cc0+cc1
    __syncthreads();

    // ---- Prologue: A(0) = layer0 step 0 (zero input, h = z) ----
    {
        float accA[4][8] = {};
        const __half* A0 = g_h0p[0];
#pragma unroll 1
        for (int i = 0; i < 2; i++) {
            __half (*S)[KP16] = SM + i * 192;
            fill64(S, A0 + i * KB, HH, tid);
            fill64(S + 64, W0h + i * KB, HH, tid);
            CP_COMMIT();
        }
        for (int i = 0; i < 8; i++) {
            if (i + 2 < 8) {
                __half (*S)[KP16] = SM + ((i + 2) % NST) * 192;
                fill64(S, A0 + (i + 2) * KB, HH, tid);
                fill64(S + 64, W0h + (i + 2) * KB, HH, tid);
                CP_COMMIT();
                CP_WAIT(2);
            } else if (i + 1 < 8) CP_WAIT(1); else CP_WAIT(0);
            __syncthreads();
            __half (*S)[KP16] = SM + (i % NST) * 192;
            mma64(S, S + 64, accA, mrow, ncol, kbase, l4, lq);
            __syncthreads();
        }
        if (ks == 0) gather(gsA, accA, mrow, ncol, l4, lq, false);
        __syncthreads();
        if (ks == 1) gather(gsA, accA, mrow, ncol, l4, lq, true);
        __syncthreads();
        cell_pass(gsA, bsum0, cc0, g_h0p[1], (__half*)0, d0, tid);
        grid_bar(NCTA);
    }

    // ---- Main loop: phase t = { B(t), A(t+1) }, one barrier per phase ----
    for (int t = 0; t < TT; t++) {
        bool doA = (t + 1 < TT);
        const __half* h0new = g_h0p[(t + 1) & 1];
        const __half* h1old = g_h1p[t & 1];
        const __half* xt    = g_xp + (long)t * BB * IND;
        int NCH = doA ? 18 : 16;

        float accA[4][8] = {}, accB[4][8] = {};

#pragma unroll 1
        for (int i = 0; i < 2; i++) {                     // prefill chunks 0,1 (SH type)
            __half (*S)[KP16] = SM + i * 192;
            fill64(S, h0new + i * KB, HH, tid);
            fill64(S + 64, W1i + i * KB, HH, tid);
            if (doA) fill64(S + 128, W0h + i * KB, HH, tid);
            CP_COMMIT();
        }
        for (int i = 0; i < NCH; i++) {
            int ip = i + 2;
            if (ip < NCH) {
                __half (*S)[KP16] = SM + (ip % NST) * 192;
                if (ip < 8) {
                    fill64(S, h0new + ip * KB, HH, tid);
                    fill64(S + 64, W1i + ip * KB, HH, tid);
                    if (doA) fill64(S + 128, W0h + ip * KB, HH, tid);
                } else if (ip < 16) {
                    fill64(S, h1old + (ip - 8) * KB, HH, tid);
                    fill64(S + 64, W1h + (ip - 8) * KB, HH, tid);
                } else {
                    fill64(S, xt + (ip - 16) * KB, IND, tid);
                    fill64(S + 64, W0x + (ip - 16) * KB, IND, tid);
                }
                CP_COMMIT();
                CP_WAIT(2);
            } else if (i + 1 < NCH) CP_WAIT(1); else CP_WAIT(0);
            __syncthreads();
            __half (*S)[KP16] = SM + (i % NST) * 192;
            if (i < 8) {
                mma64(S, S + 64, accB, mrow, ncol, kbase, l4, lq);
                if (doA) mma64(S, S + 128, accA, mrow, ncol, kbase, l4, lq);
            } else if (i < 16) {
                mma64(S, S + 64, accB, mrow, ncol, kbase, l4, lq);
            } else {
                mma64(S, S + 64, accA, mrow, ncol, kbase, l4, lq);
            }
            __syncthreads();
        }

        // epilogues: gather (K-split reduce) then cells
        if (ks == 0) {
            gather(gsB, accB, mrow, ncol, l4, lq, false);
            if (doA) gather(gsA, accA, mrow, ncol, l4, lq, false);
        }
        __syncthreads();
        if (ks == 1) {
            gather(gsB, accB, mrow, ncol, l4, lq, true);
            if (doA) gather(gsA, accA, mrow, ncol, l4, lq, true);
        }
        __syncthreads();
        cell_pass(gsB, bsum1, cc1, g_h1p[(t + 1) & 1],
                  g_h1all + (long)t * BB * HH, d0, tid);
        if (doA) {
            cell_pass(gsA, bsum0, cc0, g_h0p[t & 1], (__half*)0, d0, tid);
            grid_bar((unsigned)(t + 2) * NCTA);
        }
    }
}

// ---------------- deferred output projection ----------------
__global__ __launch_bounds__(256) void out_kernel(
    const float* __restrict__ blin, float* __restrict__ out)
{
    extern __shared__ __align__(16) unsigned char smraw[];
    __half (*SM)[KP16] = (__half(*)[KP16])smraw;
    float (*gs)[72] = (float(*)[72])smraw;

    int tid = threadIdx.x, lane = tid & 31, w = tid >> 5;
    int ks = w >> 2, my = (w >> 1) & 1, nx = w & 1;
    int mrow = my * 32, ncol = nx * 32, kbase = ks * 64;
    int l4 = lane >> 2, lq = lane & 3;
    int m0 = blockIdx.x * 64, c0 = blockIdx.y * 64;

    const __half* A  = g_h1all + (long)m0 * HH;
    const __half* Wb = g_Wlp + (long)blockIdx.y * 64 * HH;
    float acc[4][8] = {};

#pragma unroll 1
    for (int i = 0; i < 2; i++) {
        __half (*S)[KP16] = SM + i * 192;
        fill64(S, A + i * KB, HH, tid);
        fill64(S + 64, Wb + i * KB, HH, tid);
        CP_COMMIT();
    }
    for (int i = 0; i < 8; i++) {
        if (i + 2 < 8) {
            __half (*S)[KP16] = SM + ((i + 2) % NST) * 192;
            fill64(S, A + (i + 2) * KB, HH, tid);
            fill64(S + 64, Wb + (i + 2) * KB, HH, tid);
            CP_COMMIT();
            CP_WAIT(2);
        } else if (i + 1 < 8) CP_WAIT(1); else CP_WAIT(0);
        __syncthreads();
        __half (*S)[KP16] = SM + (i % NST) * 192;
        mma64(S, S + 64, acc, mrow, ncol, kbase, l4, lq);
        __syncthreads();
    }

    if (ks == 0) gather(gs, acc, mrow, ncol, l4, lq, false);
    __syncthreads();
    if (ks == 1) gather(gs, acc, mrow, ncol, l4, lq, true);
    __syncthreads();

#pragma unroll
    for (int s = 0; s < 16; s++) {
        int idx = tid + s * 256;
        int r = idx >> 6, c = idx & 63;
        int m = m0 + r;
        int tq = m >> 6, b = m & 63;
        int o = c0 + c;
        out[(long)b * (TT * OUTD) + tq * OUTD + o] = gs[r][c] + blin[o];
    }
}

// ---------------- host launcher ----------------
extern "C" void kernel_launch(void* const* d_in, const int* in_sizes, int n_in,
                              void* d_out, int out_size)
{
    const float* z    = (const float*)d_in[0];
    const float* x    = (const float*)d_in[1];
    const float* Wih0 = (const float*)d_in[2];
    const float* Whh0 = (const float*)d_in[3];
    const float* bih0 = (const float*)d_in[4];
    const float* bhh0 = (const float*)d_in[5];
    const float* Wih1 = (const float*)d_in[6];
    const float* Whh1 = (const float*)d_in[7];
    const float* bih1 = (const float*)d_in[8];
    const float* bhh1 = (const float*)d_in[9];
    const float* Wlin = (const float*)d_in[10];
    const float* blin = (const float*)d_in[11];
    float* out = (float*)d_out;

    const int SMEM_TILES = NST * 192 * KP16 * 2;              // 165,888
    const int SMEM_MAIN  = SMEM_TILES + (128 + 2048) * 4;     // +8,704
    cudaFuncSetAttribute(lstm_persist, cudaFuncAttributeMaxDynamicSharedMemorySize, SMEM_MAIN);
    cudaFuncSetAttribute(out_kernel,   cudaFuncAttributeMaxDynamicSharedMemorySize, SMEM_TILES);

    __half* dW1i; cudaGetSymbolAddress((void**)&dW1i, g_W1i);
    __half* dW0h; cudaGetSymbolAddress((void**)&dW0h, g_W0h);
    __half* dW1h; cudaGetSymbolAddress((void**)&dW1h, g_W1h);
    __half* dW0x; cudaGetSymbolAddress((void**)&dW0x, g_W0x);
    __half* dWlp; cudaGetSymbolAddress((void**)&dWlp, g_Wlp);

    init_kernel<<<64, 1024>>>(z);
    pack_w<<<2048, 256>>>(Wih1, dW1i, HH, NCTA * 64 * HH);
    pack_w<<<2048, 256>>>(Whh0, dW0h, HH, NCTA * 64 * HH);
    pack_w<<<2048, 256>>>(Whh1, dW1h, HH, NCTA * 64 * HH);
    pack_w<<<1024, 256>>>(Wih0, dW0x, IND, NCTA * 64 * IND);
    pack_wl<<<256, 256>>>(Wlin, dWlp, HH, (OUTD / 64) * 64 * HH);
    pack_x<<<2048, 256>>>(x);

    lstm_persist<<<NCTA, 256, SMEM_MAIN>>>(bih0, bhh0, bih1, bhh1);
    out_kernel<<<dim3(TT * BB / 64, OUTD / 64), 256, SMEM_TILES>>>(blin, out);
}

// round 8
// speedup vs baseline: 1.3897x; 1.3897x over previous
#include <cuda_runtime.h>
#include <cuda_fp16.h>
#include <stdint.h>
#include <math.h>

#define BB   64
#define TT   512
#define IND  256
#define OUTD 256
#define HH   1024
#define NCTA 128
#define KB   128          // fp16 elements per K-chunk
#define KP16 144          // smem row stride (halfs) = 288B, conflict-free LDS.64
#define NST  3            // pipeline stages
#define SROW 128          // rows per stage: 64 A + 32 B1 + 32 B2

// ---------------- persistent device state ----------------
__device__ __half   g_h0p[2][BB * HH];
__device__ __half   g_h1p[2][BB * HH];
__device__ __half   g_h1all[(long)TT * BB * HH];
__device__ __half   g_xp[(long)TT * BB * IND];
__device__ __half   g_W0h[NCTA * 32 * HH];
__device__ __half   g_W0x[NCTA * 32 * IND];
__device__ __half   g_W1i[NCTA * 32 * HH];
__device__ __half   g_W1h[NCTA * 32 * HH];
__device__ __half   g_Wlp[(OUTD / 32) * 32 * HH];
__device__ unsigned g_cnt[256];               // 8 counters on distinct 128B lines

// ---------------- helpers ----------------
__device__ __forceinline__ float sigm(float v) { return 1.f / (1.f + __expf(-v)); }

// k-permutation within each 16-group: lane quad (2q,2q+1,2q+8,2q+9) contiguous.
__device__ __forceinline__ int kpos16(int k) {
    int q = k >> 1, b = k & 1;
    return ((q & 3) << 2) | ((q >> 2) << 1) | b;
}
__device__ __forceinline__ int kinv16(int p) {
    int b = p & 1, hi = (p >> 1) & 1, mid = (p >> 2) & 3;
    return 2 * (mid | (hi << 2)) + b;
}
__device__ __forceinline__ long pk_full(int k) { return (k & ~15) + kpos16(k & 15); }

__device__ __forceinline__ void cp_async16(void* dst, const void* src) {
    uint32_t d = (uint32_t)__cvta_generic_to_shared(dst);
    asm volatile("cp.async.cg.shared.global [%0], [%1], 16;\n" :: "r"(d), "l"(src));
}
#define CP_COMMIT() asm volatile("cp.async.commit_group;\n" ::: "memory")
#define CP_WAIT(N)  asm volatile("cp.async.wait_group %0;\n" :: "n"(N) : "memory")

__device__ __forceinline__ unsigned ld_acq(const unsigned* p) {
    unsigned v;
    asm volatile("ld.acquire.gpu.global.u32 %0, [%1];" : "=r"(v) : "l"(p) : "memory");
    return v;
}

// Distributed-counter grid barrier (8 counters on separate L2 lines).
__device__ __forceinline__ void grid_bar(unsigned target) {
    __syncthreads();
    if (threadIdx.x == 0) {
        __threadfence();
        atomicAdd(&g_cnt[(blockIdx.x & 7) << 5], 1u);
        unsigned s;
        do {
            s = 0;
#pragma unroll
            for (int i = 0; i < 8; i++) s += ld_acq(&g_cnt[i << 5]);
        } while (s < target);
    }
    __syncthreads();
}

__device__ __forceinline__ void hmma(float* c, uint32_t a0, uint32_t a1, uint32_t a2,
                                     uint32_t a3, uint32_t b0, uint32_t b1) {
    asm volatile(
        "mma.sync.aligned.m16n8k16.row.col.f32.f16.f16.f32 "
        "{%0,%1,%2,%3}, {%4,%5,%6,%7}, {%8,%9}, {%0,%1,%2,%3};"
        : "+f"(c[0]), "+f"(c[1]), "+f"(c[2]), "+f"(c[3])
        : "r"(a0), "r"(a1), "r"(a2), "r"(a3), "r"(b0), "r"(b1));
}

// Fill a 64-row x 128-half tile (4 x 16B per thread).
__device__ __forceinline__ void fill64(__half (*S)[KP16], const __half* __restrict__ src,
                                       int ld, int tid) {
#pragma unroll
    for (int it = 0; it < 4; it++) {
        int idx = tid + it * 256;
        int row = idx >> 4;
        int seg = (idx & 15) << 3;
        cp_async16(&S[row][seg], src + (long)row * ld + seg);
    }
}
// Fill a 32-row x 128-half tile (2 x 16B per thread).
__device__ __forceinline__ void fill32(__half (*S)[KP16], const __half* __restrict__ src,
                                       int ld, int tid) {
#pragma unroll
    for (int it = 0; it < 2; it++) {
        int idx = tid + it * 256;
        int row = idx >> 4;
        int seg = (idx & 15) << 3;
        cp_async16(&S[row][seg], src + (long)row * ld + seg);
    }
}

// Warp m16n16 over full KB against one B tile.
__device__ __forceinline__ void mma_one(const __half (*A)[KP16], const __half (*B)[KP16],
                                        float cacc[2][4], int mrow, int nw, int l4, int lq) {
#pragma unroll
    for (int g = 0; g < KB / 16; g++) {
        int off = g * 16 + 4 * lq;
        uint2 va  = *(const uint2*)&A[mrow + l4][off];
        uint2 vb2 = *(const uint2*)&A[mrow + 8 + l4][off];
#pragma unroll
        for (int nt = 0; nt < 2; nt++) {
            uint2 vb = *(const uint2*)&B[nw + nt * 8 + l4][off];
            hmma(&cacc[nt][0], va.x, vb2.x, va.y, vb2.y, vb.x, vb.y);
        }
    }
}

// Warp m16n16 over full KB against TWO B tiles sharing the same A fragments.
__device__ __forceinline__ void mma_dual(const __half (*A)[KP16],
                                         const __half (*B1)[KP16], const __half (*B2)[KP16],
                                         float caccB[2][4], float caccA[2][4],
                                         int mrow, int nw, int l4, int lq) {
#pragma unroll
    for (int g = 0; g < KB / 16; g++) {
        int off = g * 16 + 4 * lq;
        uint2 va  = *(const uint2*)&A[mrow + l4][off];
        uint2 vb2 = *(const uint2*)&A[mrow + 8 + l4][off];
#pragma unroll
        for (int nt = 0; nt < 2; nt++) {
            uint2 vb = *(const uint2*)&B1[nw + nt * 8 + l4][off];
            hmma(&caccB[nt][0], va.x, vb2.x, va.y, vb2.y, vb.x, vb.y);
        }
#pragma unroll
        for (int nt = 0; nt < 2; nt++) {
            uint2 vb = *(const uint2*)&B2[nw + nt * 8 + l4][off];
            hmma(&caccA[nt][0], va.x, vb2.x, va.y, vb2.y, vb.x, vb.y);
        }
    }
}

// Gate gather: 8 warps cover disjoint m16xn16 regions -> one pass.
__device__ __forceinline__ void gather(float (*gs)[33], float cacc[2][4],
                                       int mrow, int nw, int l4, int lq) {
#pragma unroll
    for (int nt = 0; nt < 2; nt++) {
        int n0 = nw + nt * 8;
        gs[mrow + l4][n0 + 2 * lq]         = cacc[nt][0];
        gs[mrow + l4][n0 + 2 * lq + 1]     = cacc[nt][1];
        gs[mrow + 8 + l4][n0 + 2 * lq]     = cacc[nt][2];
        gs[mrow + 8 + l4][n0 + 2 * lq + 1] = cacc[nt][3];
    }
}

// LSTM cell over the CTA's 8 dims x 64 rows (2 elems/thread).
__device__ __forceinline__ void cell_pass(const float (*gs)[33], const float* bs,
                                          float (*cc)[8], __half* dst, __half* hist,
                                          int d0, int tid) {
#pragma unroll
    for (int s = 0; s < 2; s++) {
        int idx = tid * 2 + s, r = idx >> 3, j = idx & 7;
        float gi = gs[r][j]      + bs[j];
        float gf = gs[r][8 + j]  + bs[8 + j];
        float gg = gs[r][16 + j] + bs[16 + j];
        float go = gs[r][24 + j] + bs[24 + j];
        float c = sigm(gf) * cc[r][j] + sigm(gi) * tanhf(gg);
        cc[r][j] = c;
        __half h = __float2half_rn(sigm(go) * tanhf(c));
        long off = (long)r * HH + pk_full(d0 + j);
        dst[off] = h;
        if (hist) hist[off] = h;
    }
}

// ---------------- init / pack kernels ----------------
__global__ void init_kernel(const float* __restrict__ z) {
    int i = blockIdx.x * blockDim.x + threadIdx.x;     // over BB*HH
    int k = i & (HH - 1);
    long pk = (long)(i & ~(HH - 1)) + pk_full(k);
    __half v = __float2half_rn(z[i]);
    g_h0p[0][pk] = v;
    g_h1p[0][pk] = v;
    if (i < 256) g_cnt[i] = 0u;
}

// dst[blk][c][kp] <- src[(c>>3)*1024 + blk*8 + (c&7)][k],  c = 0..31
__global__ void pack_w(const float* __restrict__ src, __half* __restrict__ dst,
                       int K, int total) {
    for (int i = blockIdx.x * blockDim.x + threadIdx.x; i < total;
         i += gridDim.x * blockDim.x) {
        int kp = i % K;
        int c  = (i / K) & 31;
        int blk = i / (K * 32);
        int k = (kp & ~15) + kinv16(kp & 15);
        int row = ((c >> 3) << 10) + (blk << 3) + (c & 7);
        dst[i] = __float2half_rn(src[(long)row * K + k]);
    }
}

// dst[blk][c][kp] <- src[blk*32+c][k]
__global__ void pack_wl(const float* __restrict__ src, __half* __restrict__ dst,
                        int K, int total) {
    for (int i = blockIdx.x * blockDim.x + threadIdx.x; i < total;
         i += gridDim.x * blockDim.x) {
        int kp = i % K;
        int c  = (i / K) & 31;
        int blk = i / (K * 32);
        int k = (kp & ~15) + kinv16(kp & 15);
        dst[i] = __float2half_rn(src[(long)(blk * 32 + c) * K + k]);
    }
}

__global__ void pack_x(const float* __restrict__ x) {
    long total = (long)TT * BB * IND;
    for (long i = blockIdx.x * (long)blockDim.x + threadIdx.x; i < total;
         i += (long)gridDim.x * blockDim.x) {
        int kp = (int)(i % IND);
        int b  = (int)((i / IND) & 63);
        int t  = (int)(i / (IND * 64));
        int k = (kp & ~15) + kinv16(kp & 15);
        g_xp[i] = __float2half_rn(x[((long)b * TT + t) * IND + k]);
    }
}

// ---------------- main persistent kernel ----------------
__global__ __launch_bounds__(256) void lstm_persist(
    const float* __restrict__ bih0, const float* __restrict__ bhh0,
    const float* __restrict__ bih1, const float* __restrict__ bhh1)
{
    extern __shared__ __align__(16) unsigned char smraw[];
    __half (*SM)[KP16] = (__half(*)[KP16])smraw;             // NST * SROW rows
    float* fext  = (float*)(smraw + NST * SROW * KP16 * 2);
    float* bsum0 = fext;
    float* bsum1 = fext + 32;
    float (*cc0)[8] = (float(*)[8])(fext + 64);              // 64 x 8
    float (*cc1)[8] = cc0 + 64;
    float (*gsB)[33] = (float(*)[33])smraw;                  // alias stage area
    float (*gsA)[33] = gsB + 64;

    int tid = threadIdx.x, lane = tid & 31, w = tid >> 5;
    int mrow = (w & 3) * 16, nw = (w >> 2) * 16;
    int l4 = lane >> 2, lq = lane & 3;
    int blk = blockIdx.x, d0 = blk * 8;

    const __half* W0h = g_W0h + (long)blk * 32 * HH;
    const __half* W0x = g_W0x + (long)blk * 32 * IND;
    const __half* W1i = g_W1i + (long)blk * 32 * HH;
    const __half* W1h = g_W1h + (long)blk * 32 * HH;

    if (tid < 32) {
        int g = tid >> 3, j = tid & 7, n = (g << 10) + d0 + j;
        bsum0[tid] = bih0[n] + bhh0[n];
        bsum1[tid] = bih1[n] + bhh1[n];
    }
    {
        int i0 = tid * 2;
        ((float*)cc0)[i0] = 0.f; ((float*)cc0)[i0 + 1] = 0.f;
        ((float*)cc1)[i0] = 0.f; ((float*)cc1)[i0 + 1] = 0.f;
    }
    __syncthreads();

    // ---- Prologue: A(0) = layer0 step 0 (zero input, h0 = z) ----
    {
        float accA[2][4] = {};
        const __half* A0 = g_h0p[0];
#pragma unroll 1
        for (int i = 0; i < 2; i++) {
            __half (*S)[KP16] = SM + i * SROW;
            fill64(S, A0 + i * KB, HH, tid);
            fill32(S + 64, W0h + i * KB, HH, tid);
            CP_COMMIT();
        }
        for (int i = 0; i < 8; i++) {
            if (i + 2 < 8) {
                __half (*S)[KP16] = SM + ((i + 2) % NST) * SROW;
                fill64(S, A0 + (i + 2) * KB, HH, tid);
                fill32(S + 64, W0h + (i + 2) * KB, HH, tid);
                CP_COMMIT();
                CP_WAIT(2);
            } else if (i + 1 < 8) CP_WAIT(1); else CP_WAIT(0);
            __syncthreads();
            __half (*S)[KP16] = SM + (i % NST) * SROW;
            mma_one(S, S + 64, accA, mrow, nw, l4, lq);
            __syncthreads();
        }
        gather(gsA, accA, mrow, nw, l4, lq);
        __syncthreads();
        cell_pass(gsA, bsum0, cc0, g_h0p[1], (__half*)0, d0, tid);
        grid_bar(NCTA);
    }

    // ---- Main loop: phase t = { B(t), A(t+1) }, ONE barrier per step ----
    for (int t = 0; t < TT; t++) {
        bool doA = (t + 1 < TT);
        const __half* h0new = g_h0p[(t + 1) & 1];
        const __half* h1old = g_h1p[t & 1];
        const __half* xt    = g_xp + (long)t * BB * IND;
        int NCH = doA ? 18 : 16;

        float accA[2][4] = {}, accB[2][4] = {};

#pragma unroll 1
        for (int i = 0; i < 2; i++) {               // prefill chunks 0,1 (shared type)
            __half (*S)[KP16] = SM + i * SROW;
            fill64(S, h0new + i * KB, HH, tid);
            fill32(S + 64, W1i + i * KB, HH, tid);
            if (doA) fill32(S + 96, W0h + i * KB, HH, tid);
            CP_COMMIT();
        }
        for (int i = 0; i < NCH; i++) {
            int ip = i + 2;
            if (ip < NCH) {
                __half (*S)[KP16] = SM + (ip % NST) * SROW;
                if (ip < 8) {
                    fill64(S, h0new + ip * KB, HH, tid);
                    fill32(S + 64, W1i + ip * KB, HH, tid);
                    if (doA) fill32(S + 96, W0h + ip * KB, HH, tid);
                } else if (ip < 16) {
                    fill64(S, h1old + (ip - 8) * KB, HH, tid);
                    fill32(S + 64, W1h + (ip - 8) * KB, HH, tid);
                } else {
                    fill64(S, xt + (ip - 16) * KB, IND, tid);
                    fill32(S + 64, W0x + (ip - 16) * KB, IND, tid);
                }
                CP_COMMIT();
                CP_WAIT(2);
            } else if (i + 1 < NCH) CP_WAIT(1); else CP_WAIT(0);
            __syncthreads();
            __half (*S)[KP16] = SM + (i % NST) * SROW;
            if (i < 8) {
                if (doA) mma_dual(S, S + 64, S + 96, accB, accA, mrow, nw, l4, lq);
                else     mma_one(S, S + 64, accB, mrow, nw, l4, lq);
            } else if (i < 16) {
                mma_one(S, S + 64, accB, mrow, nw, l4, lq);
            } else {
                mma_one(S, S + 64, accA, mrow, nw, l4, lq);
            }
            __syncthreads();
        }

        // epilogue
        gather(gsB, accB, mrow, nw, l4, lq);
        if (doA) gather(gsA, accA, mrow, nw, l4, lq);
        __syncthreads();
        cell_pass(gsB, bsum1, cc1, g_h1p[(t + 1) & 1],
                  g_h1all + (long)t * BB * HH, d0, tid);
        if (doA) {
            cell_pass(gsA, bsum0, cc0, g_h0p[t & 1], (__half*)0, d0, tid);
            grid_bar((unsigned)(t + 2) * NCTA);
        }
    }
}

// ---------------- deferred output projection ----------------
__global__ __launch_bounds__(256) void out_kernel(
    const float* __restrict__ blin, float* __restrict__ out)
{
    extern __shared__ __align__(16) unsigned char smraw[];
    __half (*SM)[KP16] = (__half(*)[KP16])smraw;
    float (*gs)[33] = (float(*)[33])smraw;

    int tid = threadIdx.x, lane = tid & 31, w = tid >> 5;
    int mrow = (w & 3) * 16, nw = (w >> 2) * 16;
    int l4 = lane >> 2, lq = lane & 3;
    int m0 = blockIdx.x * 64, c0 = blockIdx.y * 32;

    const __half* A  = g_h1all + (long)m0 * HH;
    const __half* Wb = g_Wlp + (long)blockIdx.y * 32 * HH;
    float acc[2][4] = {};

#pragma unroll 1
    for (int i = 0; i < 2; i++) {
        __half (*S)[KP16] = SM + i * SROW;
        fill64(S, A + i * KB, HH, tid);
        fill32(S + 64, Wb + i * KB, HH, tid);
        CP_COMMIT();
    }
    for (int i = 0; i < 8; i++) {
        if (i + 2 < 8) {
            __half (*S)[KP16] = SM + ((i + 2) % NST) * SROW;
            fill64(S, A + (i + 2) * KB, HH, tid);
            fill32(S + 64, Wb + (i + 2) * KB, HH, tid);
            CP_COMMIT();
            CP_WAIT(2);
        } else if (i + 1 < 8) CP_WAIT(1); else CP_WAIT(0);
        __syncthreads();
        __half (*S)[KP16] = SM + (i % NST) * SROW;
        mma_one(S, S + 64, acc, mrow, nw, l4, lq);
        __syncthreads();
    }

    gather(gs, acc, mrow, nw, l4, lq);
    __syncthreads();

#pragma unroll
    for (int s = 0; s < 8; s++) {
        int idx = tid + s * 256;
        int r = idx >> 5, c = idx & 31;
        int m = m0 + r;
        int tq = m >> 6, b = m & 63;
        int o = c0 + c;
        out[(long)b * (TT * OUTD) + tq * OUTD + o] = gs[r][c] + blin[o];
    }
}

// ---------------- host launcher ----------------
extern "C" void kernel_launch(void* const* d_in, const int* in_sizes, int n_in,
                              void* d_out, int out_size)
{
    const float* z    = (const float*)d_in[0];
    const float* x    = (const float*)d_in[1];
    const float* Wih0 = (const float*)d_in[2];
    const float* Whh0 = (const float*)d_in[3];
    const float* bih0 = (const float*)d_in[4];
    const float* bhh0 = (const float*)d_in[5];
    const float* Wih1 = (const float*)d_in[6];
    const float* Whh1 = (const float*)d_in[7];
    const float* bih1 = (const float*)d_in[8];
    const float* bhh1 = (const float*)d_in[9];
    const float* Wlin = (const float*)d_in[10];
    const float* blin = (const float*)d_in[11];
    float* out = (float*)d_out;

    const int SMEM_TILES = NST * SROW * KP16 * 2;            // 110,592
    const int SMEM_MAIN  = SMEM_TILES + (64 + 1024) * 4;     // +4,352
    cudaFuncSetAttribute(lstm_persist, cudaFuncAttributeMaxDynamicSharedMemorySize, SMEM_MAIN);
    cudaFuncSetAttribute(out_kernel,   cudaFuncAttributeMaxDynamicSharedMemorySize, SMEM_TILES);

    __half* dW0h; cudaGetSymbolAddress((void**)&dW0h, g_W0h);
    __half* dW0x; cudaGetSymbolAddress((void**)&dW0x, g_W0x);
    __half* dW1i; cudaGetSymbolAddress((void**)&dW1i, g_W1i);
    __half* dW1h; cudaGetSymbolAddress((void**)&dW1h, g_W1h);
    __half* dWlp; cudaGetSymbolAddress((void**)&dWlp, g_Wlp);

    init_kernel<<<64, 1024>>>(z);
    pack_w<<<2048, 256>>>(Whh0, dW0h, HH, NCTA * 32 * HH);
    pack_w<<<1024, 256>>>(Wih0, dW0x, IND, NCTA * 32 * IND);
    pack_w<<<2048, 256>>>(Wih1, dW1i, HH, NCTA * 32 * HH);
    pack_w<<<2048, 256>>>(Whh1, dW1h, HH, NCTA * 32 * HH);
    pack_wl<<<256, 256>>>(Wlin, dWlp, HH, (OUTD / 32) * 32 * HH);
    pack_x<<<2048, 256>>>(x);

    lstm_persist<<<NCTA, 256, SMEM_MAIN>>>(bih0, bhh0, bih1, bhh1);
    out_kernel<<<dim3(TT * BB / 64, OUTD / 32), 256, SMEM_TILES>>>(blin, out);
}

// round 9
// speedup vs baseline: 1.3911x; 1.0010x over previous
#include <cuda_runtime.h>
#include <cuda_fp16.h>
#include <stdint.h>
#include <math.h>

#define BB   64
#define TT   512
#define IND  256
#define OUTD 256
#define HH   1024
#define NCTA 128
#define KB   128          // fp16 elements per K-chunk
#define KP16 144          // smem row stride (halfs) = 288B, conflict-free LDS.64
#define NST  3            // pipeline stages
#define SROW 128          // rows per stage: 64 A + 32 B1 + 32 B2

// ---------------- persistent device state ----------------
__device__ __half   g_h0p[2][BB * HH];
__device__ __half   g_h1p[2][BB * HH];
__device__ __half   g_h1all[(long)TT * BB * HH];
__device__ __half   g_xp[(long)TT * BB * IND];
__device__ __half   g_W0h[NCTA * 32 * HH];
__device__ __half   g_W0x[NCTA * 32 * IND];
__device__ __half   g_W1i[NCTA * 32 * HH];
__device__ __half   g_W1h[NCTA * 32 * HH];
__device__ __half   g_Wlp[(OUTD / 32) * 32 * HH];
__device__ unsigned g_cnt[256];               // 8 counters on distinct 128B lines

// ---------------- helpers ----------------
__device__ __forceinline__ float sigm(float v) { return 1.f / (1.f + __expf(-v)); }

// k-permutation within each 16-group: lane quad (2q,2q+1,2q+8,2q+9) contiguous.
__device__ __forceinline__ int kpos16(int k) {
    int q = k >> 1, b = k & 1;
    return ((q & 3) << 2) | ((q >> 2) << 1) | b;
}
__device__ __forceinline__ int kinv16(int p) {
    int b = p & 1, hi = (p >> 1) & 1, mid = (p >> 2) & 3;
    return 2 * (mid | (hi << 2)) + b;
}
__device__ __forceinline__ long pk_full(int k) { return (k & ~15) + kpos16(k & 15); }

__device__ __forceinline__ void cp_async16(void* dst, const void* src) {
    uint32_t d = (uint32_t)__cvta_generic_to_shared(dst);
    asm volatile("cp.async.cg.shared.global [%0], [%1], 16;\n" :: "r"(d), "l"(src));
}
#define CP_COMMIT() asm volatile("cp.async.commit_group;\n" ::: "memory")
#define CP_WAIT(N)  asm volatile("cp.async.wait_group %0;\n" :: "n"(N) : "memory")

__device__ __forceinline__ unsigned ld_acq(const unsigned* p) {
    unsigned v;
    asm volatile("ld.acquire.gpu.global.u32 %0, [%1];" : "=r"(v) : "l"(p) : "memory");
    return v;
}

// Distributed-counter grid barrier (8 counters on separate L2 lines).
__device__ __forceinline__ void grid_bar(unsigned target) {
    __syncthreads();
    if (threadIdx.x == 0) {
        __threadfence();
        atomicAdd(&g_cnt[(blockIdx.x & 7) << 5], 1u);
        unsigned s;
        do {
            s = 0;
#pragma unroll
            for (int i = 0; i < 8; i++) s += ld_acq(&g_cnt[i << 5]);
        } while (s < target);
    }
    __syncthreads();
}

__device__ __forceinline__ void hmma(float* c, uint32_t a0, uint32_t a1, uint32_t a2,
                                     uint32_t a3, uint32_t b0, uint32_t b1) {
    asm volatile(
        "mma.sync.aligned.m16n8k16.row.col.f32.f16.f16.f32 "
        "{%0,%1,%2,%3}, {%4,%5,%6,%7}, {%8,%9}, {%0,%1,%2,%3};"
        : "+f"(c[0]), "+f"(c[1]), "+f"(c[2]), "+f"(c[3])
        : "r"(a0), "r"(a1), "r"(a2), "r"(a3), "r"(b0), "r"(b1));
}

// Fill a 64-row x 128-half tile (4 x 16B per thread).
__device__ __forceinline__ void fill64(__half (*S)[KP16], const __half* __restrict__ src,
                                       int ld, int tid) {
#pragma unroll
    for (int it = 0; it < 4; it++) {
        int idx = tid + it * 256;
        int row = idx >> 4;
        int seg = (idx & 15) << 3;
        cp_async16(&S[row][seg], src + (long)row * ld + seg);
    }
}
// Fill a 32-row x 128-half tile (2 x 16B per thread).
__device__ __forceinline__ void fill32(__half (*S)[KP16], const __half* __restrict__ src,
                                       int ld, int tid) {
#pragma unroll
    for (int it = 0; it < 2; it++) {
        int idx = tid + it * 256;
        int row = idx >> 4;
        int seg = (idx & 15) << 3;
        cp_async16(&S[row][seg], src + (long)row * ld + seg);
    }
}

// Warp m16n16 over full KB against one B tile.
__device__ __forceinline__ void mma_one(const __half (*A)[KP16], const __half (*B)[KP16],
                                        float cacc[2][4], int mrow, int nw, int l4, int lq) {
#pragma unroll
    for (int g = 0; g < KB / 16; g++) {
        int off = g * 16 + 4 * lq;
        uint2 va  = *(const uint2*)&A[mrow + l4][off];
        uint2 vb2 = *(const uint2*)&A[mrow + 8 + l4][off];
#pragma unroll
        for (int nt = 0; nt < 2; nt++) {
            uint2 vb = *(const uint2*)&B[nw + nt * 8 + l4][off];
            hmma(&cacc[nt][0], va.x, vb2.x, va.y, vb2.y, vb.x, vb.y);
        }
    }
}

// Warp m16n16 over full KB against TWO B tiles sharing the same A fragments.
__device__ __forceinline__ void mma_dual(const __half (*A)[KP16],
                                         const __half (*B1)[KP16], const __half (*B2)[KP16],
                                         float caccB[2][4], float caccA[2][4],
                                         int mrow, int nw, int l4, int lq) {
#pragma unroll
    for (int g = 0; g < KB / 16; g++) {
        int off = g * 16 + 4 * lq;
        uint2 va  = *(const uint2*)&A[mrow + l4][off];
        uint2 vb2 = *(const uint2*)&A[mrow + 8 + l4][off];
#pragma unroll
        for (int nt = 0; nt < 2; nt++) {
            uint2 vb = *(const uint2*)&B1[nw + nt * 8 + l4][off];
            hmma(&caccB[nt][0], va.x, vb2.x, va.y, vb2.y, vb.x, vb.y);
        }
#pragma unroll
        for (int nt = 0; nt < 2; nt++) {
            uint2 vb = *(const uint2*)&B2[nw + nt * 8 + l4][off];
            hmma(&caccA[nt][0], va.x, vb2.x, va.y, vb2.y, vb.x, vb.y);
        }
    }
}

// Gate gather: 8 warps cover disjoint m16xn16 regions -> one pass.
__device__ __forceinline__ void gather(float (*gs)[33], float cacc[2][4],
                                       int mrow, int nw, int l4, int lq) {
#pragma unroll
    for (int nt = 0; nt < 2; nt++) {
        int n0 = nw + nt * 8;
        gs[mrow + l4][n0 + 2 * lq]         = cacc[nt][0];
        gs[mrow + l4][n0 + 2 * lq + 1]     = cacc[nt][1];
        gs[mrow + 8 + l4][n0 + 2 * lq]     = cacc[nt][2];
        gs[mrow + 8 + l4][n0 + 2 * lq + 1] = cacc[nt][3];
    }
}

// LSTM cell over the CTA's 8 dims x 64 rows (2 elems/thread).
__device__ __forceinline__ void cell_pass(const float (*gs)[33], const float* bs,
                                          float (*cc)[8], __half* dst, __half* hist,
                                          int d0, int tid) {
#pragma unroll
    for (int s = 0; s < 2; s++) {
        int idx = tid * 2 + s, r = idx >> 3, j = idx & 7;
        float gi = gs[r][j]      + bs[j];
        float gf = gs[r][8 + j]  + bs[8 + j];
        float gg = gs[r][16 + j] + bs[16 + j];
        float go = gs[r][24 + j] + bs[24 + j];
        float c = sigm(gf) * cc[r][j] + sigm(gi) * tanhf(gg);
        cc[r][j] = c;
        __half h = __float2half_rn(sigm(go) * tanhf(c));
        long off = (long)r * HH + pk_full(d0 + j);
        dst[off] = h;
        if (hist) hist[off] = h;
    }
}

// ---------------- init / pack kernels ----------------
__global__ void init_kernel(const float* __restrict__ z) {
    int i = blockIdx.x * blockDim.x + threadIdx.x;     // over BB*HH
    int k = i & (HH - 1);
    long pk = (long)(i & ~(HH - 1)) + pk_full(k);
    __half v = __float2half_rn(z[i]);
    g_h0p[0][pk] = v;
    g_h1p[0][pk] = v;
    if (i < 256) g_cnt[i] = 0u;
}

// dst[blk][c][kp] <- src[(c>>3)*1024 + blk*8 + (c&7)][k],  c = 0..31
__global__ void pack_w(const float* __restrict__ src, __half* __restrict__ dst,
                       int K, int total) {
    for (int i = blockIdx.x * blockDim.x + threadIdx.x; i < total;
         i += gridDim.x * blockDim.x) {
        int kp = i % K;
        int c  = (i / K) & 31;
        int blk = i / (K * 32);
        int k = (kp & ~15) + kinv16(kp & 15);
        int row = ((c >> 3) << 10) + (blk << 3) + (c & 7);
        dst[i] = __float2half_rn(src[(long)row * K + k]);
    }
}

// dst[blk][c][kp] <- src[blk*32+c][k]
__global__ void pack_wl(const float* __restrict__ src, __half* __restrict__ dst,
                        int K, int total) {
    for (int i = blockIdx.x * blockDim.x + threadIdx.x; i < total;
         i += gridDim.x * blockDim.x) {
        int kp = i % K;
        int c  = (i / K) & 31;
        int blk = i / (K * 32);
        int k = (kp & ~15) + kinv16(kp & 15);
        dst[i] = __float2half_rn(src[(long)(blk * 32 + c) * K + k]);
    }
}

__global__ void pack_x(const float* __restrict__ x) {
    long total = (long)TT * BB * IND;
    for (long i = blockIdx.x * (long)blockDim.x + threadIdx.x; i < total;
         i += (long)gridDim.x * blockDim.x) {
        int kp = (int)(i % IND);
        int b  = (int)((i / IND) & 63);
        int t  = (int)(i / (IND * 64));
        int k = (kp & ~15) + kinv16(kp & 15);
        g_xp[i] = __float2half_rn(x[((long)b * TT + t) * IND + k]);
    }
}

// ---------------- main persistent kernel ----------------
__global__ __launch_bounds__(256) void lstm_persist(
    const float* __restrict__ bih0, const float* __restrict__ bhh0,
    const float* __restrict__ bih1, const float* __restrict__ bhh1)
{
    extern __shared__ __align__(16) unsigned char smraw[];
    __half (*SM)[KP16] = (__half(*)[KP16])smraw;             // NST * SROW rows
    float* fext  = (float*)(smraw + NST * SROW * KP16 * 2);
    float* bsum0 = fext;
    float* bsum1 = fext + 32;
    float (*cc0)[8] = (float(*)[8])(fext + 64);              // 64 x 8
    float (*cc1)[8] = cc0 + 64;
    float (*gsB)[33] = (float(*)[33])smraw;                  // alias stage area
    float (*gsA)[33] = gsB + 64;

    int tid = threadIdx.x, lane = tid & 31, w = tid >> 5;
    int mrow = (w & 3) * 16, nw = (w >> 2) * 16;
    int l4 = lane >> 2, lq = lane & 3;
    int blk = blockIdx.x, d0 = blk * 8;

    const __half* W0h = g_W0h + (long)blk * 32 * HH;
    const __half* W0x = g_W0x + (long)blk * 32 * IND;
    const __half* W1i = g_W1i + (long)blk * 32 * HH;
    const __half* W1h = g_W1h + (long)blk * 32 * HH;

    if (tid < 32) {
        int g = tid >> 3, j = tid & 7, n = (g << 10) + d0 + j;
        bsum0[tid] = bih0[n] + bhh0[n];
        bsum1[tid] = bih1[n] + bhh1[n];
    }
    {
        int i0 = tid * 2;
        ((float*)cc0)[i0] = 0.f; ((float*)cc0)[i0 + 1] = 0.f;
        ((float*)cc1)[i0] = 0.f; ((float*)cc1)[i0 + 1] = 0.f;
    }
    __syncthreads();

    // ---- Prologue: A(0) = layer0 step 0 (zero input, h0 = z) ----
    {
        float accA[2][4] = {};
        const __half* A0 = g_h0p[0];
#pragma unroll 1
        for (int i = 0; i < 2; i++) {
            __half (*S)[KP16] = SM + i * SROW;
            fill64(S, A0 + i * KB, HH, tid);
            fill32(S + 64, W0h + i * KB, HH, tid);
            CP_COMMIT();
        }
        for (int i = 0; i < 8; i++) {
            if (i + 2 < 8) {
                __half (*S)[KP16] = SM + ((i + 2) % NST) * SROW;
                fill64(S, A0 + (i + 2) * KB, HH, tid);
                fill32(S + 64, W0h + (i + 2) * KB, HH, tid);
                CP_COMMIT();
                CP_WAIT(2);
            } else if (i + 1 < 8) CP_WAIT(1); else CP_WAIT(0);
            __syncthreads();
            __half (*S)[KP16] = SM + (i % NST) * SROW;
            mma_one(S, S + 64, accA, mrow, nw, l4, lq);
            __syncthreads();
        }
        gather(gsA, accA, mrow, nw, l4, lq);
        __syncthreads();
        cell_pass(gsA, bsum0, cc0, g_h0p[1], (__half*)0, d0, tid);
        grid_bar(NCTA);
    }

    // ---- Main loop: phase t = { B(t), A(t+1) }, ONE barrier per step ----
    for (int t = 0; t < TT; t++) {
        bool doA = (t + 1 < TT);
        const __half* h0new = g_h0p[(t + 1) & 1];
        const __half* h1old = g_h1p[t & 1];
        const __half* xt    = g_xp + (long)t * BB * IND;
        int NCH = doA ? 18 : 16;

        float accA[2][4] = {}, accB[2][4] = {};

#pragma unroll 1
        for (int i = 0; i < 2; i++) {               // prefill chunks 0,1 (shared type)
            __half (*S)[KP16] = SM + i * SROW;
            fill64(S, h0new + i * KB, HH, tid);
            fill32(S + 64, W1i + i * KB, HH, tid);
            if (doA) fill32(S + 96, W0h + i * KB, HH, tid);
            CP_COMMIT();
        }
        for (int i = 0; i < NCH; i++) {
            int ip = i + 2;
            if (ip < NCH) {
                __half (*S)[KP16] = SM + (ip % NST) * SROW;
                if (ip < 8) {
                    fill64(S, h0new + ip * KB, HH, tid);
                    fill32(S + 64, W1i + ip * KB, HH, tid);
                    if (doA) fill32(S + 96, W0h + ip * KB, HH, tid);
                } else if (ip < 16) {
                    fill64(S, h1old + (ip - 8) * KB, HH, tid);
                    fill32(S + 64, W1h + (ip - 8) * KB, HH, tid);
                } else {
                    fill64(S, xt + (ip - 16) * KB, IND, tid);
                    fill32(S + 64, W0x + (ip - 16) * KB, IND, tid);
                }
                CP_COMMIT();
                CP_WAIT(2);
            } else if (i + 1 < NCH) CP_WAIT(1); else CP_WAIT(0);
            __syncthreads();
            __half (*S)[KP16] = SM + (i % NST) * SROW;
            if (i < 8) {
                if (doA) mma_dual(S, S + 64, S + 96, accB, accA, mrow, nw, l4, lq);
                else     mma_one(S, S + 64, accB, mrow, nw, l4, lq);
            } else if (i < 16) {
                mma_one(S, S + 64, accB, mrow, nw, l4, lq);
            } else {
                mma_one(S, S + 64, accA, mrow, nw, l4, lq);
            }
            __syncthreads();
        }

        // epilogue
        gather(gsB, accB, mrow, nw, l4, lq);
        if (doA) gather(gsA, accA, mrow, nw, l4, lq);
        __syncthreads();
        cell_pass(gsB, bsum1, cc1, g_h1p[(t + 1) & 1],
                  g_h1all + (long)t * BB * HH, d0, tid);
        if (doA) {
            cell_pass(gsA, bsum0, cc0, g_h0p[t & 1], (__half*)0, d0, tid);
            grid_bar((unsigned)(t + 2) * NCTA);
        }
    }
}

// ---------------- deferred output projection ----------------
__global__ __launch_bounds__(256) void out_kernel(
    const float* __restrict__ blin, float* __restrict__ out)
{
    extern __shared__ __align__(16) unsigned char smraw[];
    __half (*SM)[KP16] = (__half(*)[KP16])smraw;
    float (*gs)[33] = (float(*)[33])smraw;

    int tid = threadIdx.x, lane = tid & 31, w = tid >> 5;
    int mrow = (w & 3) * 16, nw = (w >> 2) * 16;
    int l4 = lane >> 2, lq = lane & 3;
    int m0 = blockIdx.x * 64, c0 = blockIdx.y * 32;

    const __half* A  = g_h1all + (long)m0 * HH;
    const __half* Wb = g_Wlp + (long)blockIdx.y * 32 * HH;
    float acc[2][4] = {};

#pragma unroll 1
    for (int i = 0; i < 2; i++) {
        __half (*S)[KP16] = SM + i * SROW;
        fill64(S, A + i * KB, HH, tid);
        fill32(S + 64, Wb + i * KB, HH, tid);
        CP_COMMIT();
    }
    for (int i = 0; i < 8; i++) {
        if (i + 2 < 8) {
            __half (*S)[KP16] = SM + ((i + 2) % NST) * SROW;
            fill64(S, A + (i + 2) * KB, HH, tid);
            fill32(S + 64, Wb + (i + 2) * KB, HH, tid);
            CP_COMMIT();
            CP_WAIT(2);
        } else if (i + 1 < 8) CP_WAIT(1); else CP_WAIT(0);
        __syncthreads();
        __half (*S)[KP16] = SM + (i % NST) * SROW;
        mma_one(S, S + 64, acc, mrow, nw, l4, lq);
        __syncthreads();
    }

    gather(gs, acc, mrow, nw, l4, lq);
    __syncthreads();

#pragma unroll
    for (int s = 0; s < 8; s++) {
        int idx = tid + s * 256;
        int r = idx >> 5, c = idx & 31;
        int m = m0 + r;
        int tq = m >> 6, b = m & 63;
        int o = c0 + c;
        out[(long)b * (TT * OUTD) + tq * OUTD + o] = gs[r][c] + blin[o];
    }
}

// ---------------- host launcher ----------------
extern "C" void kernel_launch(void* const* d_in, const int* in_sizes, int n_in,
                              void* d_out, int out_size)
{
    const float* z    = (const float*)d_in[0];
    const float* x    = (const float*)d_in[1];
    const float* Wih0 = (const float*)d_in[2];
    const float* Whh0 = (const float*)d_in[3];
    const float* bih0 = (const float*)d_in[4];
    const float* bhh0 = (const float*)d_in[5];
    const float* Wih1 = (const float*)d_in[6];
    const float* Whh1 = (const float*)d_in[7];
    const float* bih1 = (const float*)d_in[8];
    const float* bhh1 = (const float*)d_in[9];
    const float* Wlin = (const float*)d_in[10];
    const float* blin = (const float*)d_in[11];
    float* out = (float*)d_out;

    const int SMEM_TILES = NST * SROW * KP16 * 2;            // 110,592
    const int SMEM_MAIN  = SMEM_TILES + (64 + 1024) * 4;     // +4,352
    cudaFuncSetAttribute(lstm_persist, cudaFuncAttributeMaxDynamicSharedMemorySize, SMEM_MAIN);
    cudaFuncSetAttribute(out_kernel,   cudaFuncAttributeMaxDynamicSharedMemorySize, SMEM_TILES);

    __half* dW0h; cudaGetSymbolAddress((void**)&dW0h, g_W0h);
    __half* dW0x; cudaGetSymbolAddress((void**)&dW0x, g_W0x);
    __half* dW1i; cudaGetSymbolAddress((void**)&dW1i, g_W1i);
    __half* dW1h; cudaGetSymbolAddress((void**)&dW1h, g_W1h);
    __half* dWlp; cudaGetSymbolAddress((void**)&dWlp, g_Wlp);

    init_kernel<<<64, 1024>>>(z);
    pack_w<<<2048, 256>>>(Whh0, dW0h, HH, NCTA * 32 * HH);
    pack_w<<<1024, 256>>>(Wih0, dW0x, IND, NCTA * 32 * IND);
    pack_w<<<2048, 256>>>(Wih1, dW1i, HH, NCTA * 32 * HH);
    pack_w<<<2048, 256>>>(Whh1, dW1h, HH, NCTA * 32 * HH);
    pack_wl<<<256, 256>>>(Wlin, dWlp, HH, (OUTD / 32) * 32 * HH);
    pack_x<<<2048, 256>>>(x);

    lstm_persist<<<NCTA, 256, SMEM_MAIN>>>(bih0, bhh0, bih1, bhh1);
    out_kernel<<<dim3(TT * BB / 64, OUTD / 32), 256, SMEM_TILES>>>(blin, out);
}

// round 10
// speedup vs baseline: 1.3934x; 1.0016x over previous
#include <cuda_runtime.h>
#include <cuda_fp16.h>
#include <stdint.h>
#include <math.h>

#define BB   64
#define TT   512
#define IND  256
#define OUTD 256
#define HH   1024
#define NCTA 128
#define KB   128          // fp16 elements per K-chunk
#define KP16 144          // smem row stride (halfs) = 288B, conflict-free LDS.64
#define NST  3            // pipeline stages
#define SROW 128          // rows per stage: 64 A + 32 B1 + 32 B2

// ---------------- persistent device state ----------------
__device__ __half   g_h0p[2][BB * HH];
__device__ __half   g_h1p[2][BB * HH];
__device__ __half   g_h1all[(long)TT * BB * HH];
__device__ __half   g_xp[(long)TT * BB * IND];
__device__ __half   g_W0h[NCTA * 32 * HH];
__device__ __half   g_W0x[NCTA * 32 * IND];
__device__ __half   g_W1i[NCTA * 32 * HH];
__device__ __half   g_W1h[NCTA * 32 * HH];
__device__ __half   g_Wlp[(OUTD / 32) * 32 * HH];
__device__ unsigned g_cnt[256];               // 8 counters on distinct 128B lines

// ---------------- helpers ----------------
__device__ __forceinline__ float sigm(float v) { return 1.f / (1.f + __expf(-v)); }

// k-permutation within each 16-group: lane quad (2q,2q+1,2q+8,2q+9) contiguous.
__device__ __forceinline__ int kpos16(int k) {
    int q = k >> 1, b = k & 1;
    return ((q & 3) << 2) | ((q >> 2) << 1) | b;
}
__device__ __forceinline__ int kinv16(int p) {
    int b = p & 1, hi = (p >> 1) & 1, mid = (p >> 2) & 3;
    return 2 * (mid | (hi << 2)) + b;
}
__device__ __forceinline__ long pk_full(int k) { return (k & ~15) + kpos16(k & 15); }

__device__ __forceinline__ void cp_async16(void* dst, const void* src) {
    uint32_t d = (uint32_t)__cvta_generic_to_shared(dst);
    asm volatile("cp.async.cg.shared.global [%0], [%1], 16;\n" :: "r"(d), "l"(src));
}
#define CP_COMMIT() asm volatile("cp.async.commit_group;\n" ::: "memory")
#define CP_WAIT(N)  asm volatile("cp.async.wait_group %0;\n" :: "n"(N) : "memory")

__device__ __forceinline__ unsigned ld_acq(const unsigned* p) {
    unsigned v;
    asm volatile("ld.acquire.gpu.global.u32 %0, [%1];" : "=r"(v) : "l"(p) : "memory");
    return v;
}

// Distributed-counter grid barrier (8 counters on separate L2 lines).
__device__ __forceinline__ void grid_bar(unsigned target) {
    __syncthreads();
    if (threadIdx.x == 0) {
        __threadfence();
        atomicAdd(&g_cnt[(blockIdx.x & 7) << 5], 1u);
        unsigned s;
        do {
            s = 0;
#pragma unroll
            for (int i = 0; i < 8; i++) s += ld_acq(&g_cnt[i << 5]);
        } while (s < target);
    }
    __syncthreads();
}

__device__ __forceinline__ void hmma(float* c, uint32_t a0, uint32_t a1, uint32_t a2,
                                     uint32_t a3, uint32_t b0, uint32_t b1) {
    asm volatile(
        "mma.sync.aligned.m16n8k16.row.col.f32.f16.f16.f32 "
        "{%0,%1,%2,%3}, {%4,%5,%6,%7}, {%8,%9}, {%0,%1,%2,%3};"
        : "+f"(c[0]), "+f"(c[1]), "+f"(c[2]), "+f"(c[3])
        : "r"(a0), "r"(a1), "r"(a2), "r"(a3), "r"(b0), "r"(b1));
}

// Fill a 64-row x 128-half tile (4 x 16B per thread).
__device__ __forceinline__ void fill64(__half (*S)[KP16], const __half* __restrict__ src,
                                       int ld, int tid) {
#pragma unroll
    for (int it = 0; it < 4; it++) {
        int idx = tid + it * 256;
        int row = idx >> 4;
        int seg = (idx & 15) << 3;
        cp_async16(&S[row][seg], src + (long)row * ld + seg);
    }
}
// Fill a 32-row x 128-half tile (2 x 16B per thread).
__device__ __forceinline__ void fill32(__half (*S)[KP16], const __half* __restrict__ src,
                                       int ld, int tid) {
#pragma unroll
    for (int it = 0; it < 2; it++) {
        int idx = tid + it * 256;
        int row = idx >> 4;
        int seg = (idx & 15) << 3;
        cp_async16(&S[row][seg], src + (long)row * ld + seg);
    }
}

// Warp m16n16 over full KB against one B tile.
__device__ __forceinline__ void mma_one(const __half (*A)[KP16], const __half (*B)[KP16],
                                        float cacc[2][4], int mrow, int nw, int l4, int lq) {
#pragma unroll
    for (int g = 0; g < KB / 16; g++) {
        int off = g * 16 + 4 * lq;
        uint2 va  = *(const uint2*)&A[mrow + l4][off];
        uint2 vb2 = *(const uint2*)&A[mrow + 8 + l4][off];
#pragma unroll
        for (int nt = 0; nt < 2; nt++) {
            uint2 vb = *(const uint2*)&B[nw + nt * 8 + l4][off];
            hmma(&cacc[nt][0], va.x, vb2.x, va.y, vb2.y, vb.x, vb.y);
        }
    }
}

// Warp m16n16 over full KB against TWO B tiles sharing the same A fragments.
__device__ __forceinline__ void mma_dual(const __half (*A)[KP16],
                                         const __half (*B1)[KP16], const __half (*B2)[KP16],
                                         float caccB[2][4], float caccA[2][4],
                                         int mrow, int nw, int l4, int lq) {
#pragma unroll
    for (int g = 0; g < KB / 16; g++) {
        int off = g * 16 + 4 * lq;
        uint2 va  = *(const uint2*)&A[mrow + l4][off];
        uint2 vb2 = *(const uint2*)&A[mrow + 8 + l4][off];
#pragma unroll
        for (int nt = 0; nt < 2; nt++) {
            uint2 vb = *(const uint2*)&B1[nw + nt * 8 + l4][off];
            hmma(&caccB[nt][0], va.x, vb2.x, va.y, vb2.y, vb.x, vb.y);
        }
#pragma unroll
        for (int nt = 0; nt < 2; nt++) {
            uint2 vb = *(const uint2*)&B2[nw + nt * 8 + l4][off];
            hmma(&caccA[nt][0], va.x, vb2.x, va.y, vb2.y, vb.x, vb.y);
        }
    }
}

// Gate gather: 8 warps cover disjoint m16xn16 regions -> one pass.
__device__ __forceinline__ void gather(float (*gs)[33], float cacc[2][4],
                                       int mrow, int nw, int l4, int lq) {
#pragma unroll
    for (int nt = 0; nt < 2; nt++) {
        int n0 = nw + nt * 8;
        gs[mrow + l4][n0 + 2 * lq]         = cacc[nt][0];
        gs[mrow + l4][n0 + 2 * lq + 1]     = cacc[nt][1];
        gs[mrow + 8 + l4][n0 + 2 * lq]     = cacc[nt][2];
        gs[mrow + 8 + l4][n0 + 2 * lq + 1] = cacc[nt][3];
    }
}

// LSTM cell over the CTA's 8 dims x 64 rows (2 elems/thread).
__device__ __forceinline__ void cell_pass(const float (*gs)[33], const float* bs,
                                          float (*cc)[8], __half* dst, __half* hist,
                                          int d0, int tid) {
#pragma unroll
    for (int s = 0; s < 2; s++) {
        int idx = tid * 2 + s, r = idx >> 3, j = idx & 7;
        float gi = gs[r][j]      + bs[j];
        float gf = gs[r][8 + j]  + bs[8 + j];
        float gg = gs[r][16 + j] + bs[16 + j];
        float go = gs[r][24 + j] + bs[24 + j];
        float c = sigm(gf) * cc[r][j] + sigm(gi) * tanhf(gg);
        cc[r][j] = c;
        __half h = __float2half_rn(sigm(go) * tanhf(c));
        long off = (long)r * HH + pk_full(d0 + j);
        dst[off] = h;
        if (hist) hist[off] = h;
    }
}

// ---------------- init / pack kernels ----------------
__global__ void init_kernel(const float* __restrict__ z) {
    int i = blockIdx.x * blockDim.x + threadIdx.x;     // over BB*HH
    int k = i & (HH - 1);
    long pk = (long)(i & ~(HH - 1)) + pk_full(k);
    __half v = __float2half_rn(z[i]);
    g_h0p[0][pk] = v;
    g_h1p[0][pk] = v;
    if (i < 256) g_cnt[i] = 0u;
}

// dst[blk][c][kp] <- src[(c>>3)*1024 + blk*8 + (c&7)][k],  c = 0..31
__global__ void pack_w(const float* __restrict__ src, __half* __restrict__ dst,
                       int K, int total) {
    for (int i = blockIdx.x * blockDim.x + threadIdx.x; i < total;
         i += gridDim.x * blockDim.x) {
        int kp = i % K;
        int c  = (i / K) & 31;
        int blk = i / (K * 32);
        int k = (kp & ~15) + kinv16(kp & 15);
        int row = ((c >> 3) << 10) + (blk << 3) + (c & 7);
        dst[i] = __float2half_rn(src[(long)row * K + k]);
    }
}

// dst[blk][c][kp] <- src[blk*32+c][k]
__global__ void pack_wl(const float* __restrict__ src, __half* __restrict__ dst,
                        int K, int total) {
    for (int i = blockIdx.x * blockDim.x + threadIdx.x; i < total;
         i += gridDim.x * blockDim.x) {
        int kp = i % K;
        int c  = (i / K) & 31;
        int blk = i / (K * 32);
        int k = (kp & ~15) + kinv16(kp & 15);
        dst[i] = __float2half_rn(src[(long)(blk * 32 + c) * K + k]);
    }
}

__global__ void pack_x(const float* __restrict__ x) {
    long total = (long)TT * BB * IND;
    for (long i = blockIdx.x * (long)blockDim.x + threadIdx.x; i < total;
         i += (long)gridDim.x * blockDim.x) {
        int kp = (int)(i % IND);
        int b  = (int)((i / IND) & 63);
        int t  = (int)(i / (IND * 64));
        int k = (kp & ~15) + kinv16(kp & 15);
        g_xp[i] = __float2half_rn(x[((long)b * TT + t) * IND + k]);
    }
}

// ---------------- main persistent kernel ----------------
__global__ __launch_bounds__(256) void lstm_persist(
    const float* __restrict__ bih0, const float* __restrict__ bhh0,
    const float* __restrict__ bih1, const float* __restrict__ bhh1)
{
    extern __shared__ __align__(16) unsigned char smraw[];
    __half (*SM)[KP16] = (__half(*)[KP16])smraw;             // NST * SROW rows
    float* fext  = (float*)(smraw + NST * SROW * KP16 * 2);
    float* bsum0 = fext;
    float* bsum1 = fext + 32;
    float (*cc0)[8] = (float(*)[8])(fext + 64);              // 64 x 8
    float (*cc1)[8] = cc0 + 64;
    float (*gsB)[33] = (float(*)[33])smraw;                  // alias stage area
    float (*gsA)[33] = gsB + 64;

    int tid = threadIdx.x, lane = tid & 31, w = tid >> 5;
    int mrow = (w & 3) * 16, nw = (w >> 2) * 16;
    int l4 = lane >> 2, lq = lane & 3;
    int blk = blockIdx.x, d0 = blk * 8;

    const __half* W0h = g_W0h + (long)blk * 32 * HH;
    const __half* W0x = g_W0x + (long)blk * 32 * IND;
    const __half* W1i = g_W1i + (long)blk * 32 * HH;
    const __half* W1h = g_W1h + (long)blk * 32 * HH;

    if (tid < 32) {
        int g = tid >> 3, j = tid & 7, n = (g << 10) + d0 + j;
        bsum0[tid] = bih0[n] + bhh0[n];
        bsum1[tid] = bih1[n] + bhh1[n];
    }
    {
        int i0 = tid * 2;
        ((float*)cc0)[i0] = 0.f; ((float*)cc0)[i0 + 1] = 0.f;
        ((float*)cc1)[i0] = 0.f; ((float*)cc1)[i0 + 1] = 0.f;
    }
    __syncthreads();

    // ---- Prologue: A(0) = layer0 step 0 (zero input, h0 = z) ----
    {
        float accA[2][4] = {};
        const __half* A0 = g_h0p[0];
#pragma unroll 1
        for (int i = 0; i < 2; i++) {
            __half (*S)[KP16] = SM + i * SROW;
            fill64(S, A0 + i * KB, HH, tid);
            fill32(S + 64, W0h + i * KB, HH, tid);
            CP_COMMIT();
        }
        for (int i = 0; i < 8; i++) {
            if (i + 2 < 8) {
                __half (*S)[KP16] = SM + ((i + 2) % NST) * SROW;
                fill64(S, A0 + (i + 2) * KB, HH, tid);
                fill32(S + 64, W0h + (i + 2) * KB, HH, tid);
                CP_COMMIT();
                CP_WAIT(2);
            } else if (i + 1 < 8) CP_WAIT(1); else CP_WAIT(0);
            __syncthreads();
            __half (*S)[KP16] = SM + (i % NST) * SROW;
            mma_one(S, S + 64, accA, mrow, nw, l4, lq);
            __syncthreads();
        }
        gather(gsA, accA, mrow, nw, l4, lq);
        __syncthreads();
        cell_pass(gsA, bsum0, cc0, g_h0p[1], (__half*)0, d0, tid);
        grid_bar(NCTA);
    }

    // ---- Main loop: phase t = { B(t), A(t+1) }, ONE barrier per step ----
    for (int t = 0; t < TT; t++) {
        bool doA = (t + 1 < TT);
        const __half* h0new = g_h0p[(t + 1) & 1];
        const __half* h1old = g_h1p[t & 1];
        const __half* xt    = g_xp + (long)t * BB * IND;
        int NCH = doA ? 18 : 16;

        float accA[2][4] = {}, accB[2][4] = {};

#pragma unroll 1
        for (int i = 0; i < 2; i++) {               // prefill chunks 0,1 (shared type)
            __half (*S)[KP16] = SM + i * SROW;
            fill64(S, h0new + i * KB, HH, tid);
            fill32(S + 64, W1i + i * KB, HH, tid);
            if (doA) fill32(S + 96, W0h + i * KB, HH, tid);
            CP_COMMIT();
        }
        for (int i = 0; i < NCH; i++) {
            int ip = i + 2;
            if (ip < NCH) {
                __half (*S)[KP16] = SM + (ip % NST) * SROW;
                if (ip < 8) {
                    fill64(S, h0new + ip * KB, HH, tid);
                    fill32(S + 64, W1i + ip * KB, HH, tid);
                    if (doA) fill32(S + 96, W0h + ip * KB, HH, tid);
                } else if (ip < 16) {
                    fill64(S, h1old + (ip - 8) * KB, HH, tid);
                    fill32(S + 64, W1h + (ip - 8) * KB, HH, tid);
                } else {
                    fill64(S, xt + (ip - 16) * KB, IND, tid);
                    fill32(S + 64, W0x + (ip - 16) * KB, IND, tid);
                }
                CP_COMMIT();
                CP_WAIT(2);
            } else if (i + 1 < NCH) CP_WAIT(1); else CP_WAIT(0);
            __syncthreads();
            __half (*S)[KP16] = SM + (i % NST) * SROW;
            if (i < 8) {
                if (doA) mma_dual(S, S + 64, S + 96, accB, accA, mrow, nw, l4, lq);
                else     mma_one(S, S + 64, accB, mrow, nw, l4, lq);
            } else if (i < 16) {
                mma_one(S, S + 64, accB, mrow, nw, l4, lq);
            } else {
                mma_one(S, S + 64, accA, mrow, nw, l4, lq);
            }
            __syncthreads();
        }

        // epilogue
        gather(gsB, accB, mrow, nw, l4, lq);
        if (doA) gather(gsA, accA, mrow, nw, l4, lq);
        __syncthreads();
        cell_pass(gsB, bsum1, cc1, g_h1p[(t + 1) & 1],
                  g_h1all + (long)t * BB * HH, d0, tid);
        if (doA) {
            cell_pass(gsA, bsum0, cc0, g_h0p[t & 1], (__half*)0, d0, tid);
            grid_bar((unsigned)(t + 2) * NCTA);
        }
    }
}

// ---------------- deferred output projection ----------------
__global__ __launch_bounds__(256) void out_kernel(
    const float* __restrict__ blin, float* __restrict__ out)
{
    extern __shared__ __align__(16) unsigned char smraw[];
    __half (*SM)[KP16] = (__half(*)[KP16])smraw;
    float (*gs)[33] = (float(*)[33])smraw;

    int tid = threadIdx.x, lane = tid & 31, w = tid >> 5;
    int mrow = (w & 3) * 16, nw = (w >> 2) * 16;
    int l4 = lane >> 2, lq = lane & 3;
    int m0 = blockIdx.x * 64, c0 = blockIdx.y * 32;

    const __half* A  = g_h1all + (long)m0 * HH;
    const __half* Wb = g_Wlp + (long)blockIdx.y * 32 * HH;
    float acc[2][4] = {};

#pragma unroll 1
    for (int i = 0; i < 2; i++) {
        __half (*S)[KP16] = SM + i * SROW;
        fill64(S, A + i * KB, HH, tid);
        fill32(S + 64, Wb + i * KB, HH, tid);
        CP_COMMIT();
    }
    for (int i = 0; i < 8; i++) {
        if (i + 2 < 8) {
            __half (*S)[KP16] = SM + ((i + 2) % NST) * SROW;
            fill64(S, A + (i + 2) * KB, HH, tid);
            fill32(S + 64, Wb + (i + 2) * KB, HH, tid);
            CP_COMMIT();
            CP_WAIT(2);
        } else if (i + 1 < 8) CP_WAIT(1); else CP_WAIT(0);
        __syncthreads();
        __half (*S)[KP16] = SM + (i % NST) * SROW;
        mma_one(S, S + 64, acc, mrow, nw, l4, lq);
        __syncthreads();
    }

    gather(gs, acc, mrow, nw, l4, lq);
    __syncthreads();

#pragma unroll
    for (int s = 0; s < 8; s++) {
        int idx = tid + s * 256;
        int r = idx >> 5, c = idx & 31;
        int m = m0 + r;
        int tq = m >> 6, b = m & 63;
        int o = c0 + c;
        out[(long)b * (TT * OUTD) + tq * OUTD + o] = gs[r][c] + blin[o];
    }
}

// ---------------- host launcher ----------------
extern "C" void kernel_launch(void* const* d_in, const int* in_sizes, int n_in,
                              void* d_out, int out_size)
{
    const float* z    = (const float*)d_in[0];
    const float* x    = (const float*)d_in[1];
    const float* Wih0 = (const float*)d_in[2];
    const float* Whh0 = (const float*)d_in[3];
    const float* bih0 = (const float*)d_in[4];
    const float* bhh0 = (const float*)d_in[5];
    const float* Wih1 = (const float*)d_in[6];
    const float* Whh1 = (const float*)d_in[7];
    const float* bih1 = (const float*)d_in[8];
    const float* bhh1 = (const float*)d_in[9];
    const float* Wlin = (const float*)d_in[10];
    const float* blin = (const float*)d_in[11];
    float* out = (float*)d_out;

    const int SMEM_TILES = NST * SROW * KP16 * 2;            // 110,592
    const int SMEM_MAIN  = SMEM_TILES + (64 + 1024) * 4;     // +4,352
    cudaFuncSetAttribute(lstm_persist, cudaFuncAttributeMaxDynamicSharedMemorySize, SMEM_MAIN);
    cudaFuncSetAttribute(out_kernel,   cudaFuncAttributeMaxDynamicSharedMemorySize, SMEM_TILES);

    __half* dW0h; cudaGetSymbolAddress((void**)&dW0h, g_W0h);
    __half* dW0x; cudaGetSymbolAddress((void**)&dW0x, g_W0x);
    __half* dW1i; cudaGetSymbolAddress((void**)&dW1i, g_W1i);
    __half* dW1h; cudaGetSymbolAddress((void**)&dW1h, g_W1h);
    __half* dWlp; cudaGetSymbolAddress((void**)&dWlp, g_Wlp);

    init_kernel<<<64, 1024>>>(z);
    pack_w<<<2048, 256>>>(Whh0, dW0h, HH, NCTA * 32 * HH);
    pack_w<<<1024, 256>>>(Wih0, dW0x, IND, NCTA * 32 * IND);
    pack_w<<<2048, 256>>>(Wih1, dW1i, HH, NCTA * 32 * HH);
    pack_w<<<2048, 256>>>(Whh1, dW1h, HH, NCTA * 32 * HH);
    pack_wl<<<256, 256>>>(Wlin, dWlp, HH, (OUTD / 32) * 32 * HH);
    pack_x<<<2048, 256>>>(x);

    lstm_persist<<<NCTA, 256, SMEM_MAIN>>>(bih0, bhh0, bih1, bhh1);
    out_kernel<<<dim3(TT * BB / 64, OUTD / 32), 256, SMEM_TILES>>>(blin, out);
}

// round 11
// speedup vs baseline: 1.5758x; 1.1309x over previous
#include <cuda_runtime.h>
#include <cuda_fp16.h>
#include <stdint.h>
#include <math.h>

#define BB   64
#define TT   512
#define IND  256
#define OUTD 256
#define HH   1024
#define NCTA 128
#define STGH 16384            // halfs per stage: A 8192 | B1 4096 | B2 4096
#define MBOFF (3 * STGH * 2)  // 98304 B: mbarriers after stages

// ---------------- persistent device state (chunk-image layouts) ----------------
__device__ __half   g_h0p[2][8 * 8192];            // [chunk][64 x 128] images
__device__ __half   g_h1p[2][8 * 8192];
__device__ __half   g_h1all[(long)TT * 8 * 8192];  // per-t h1 images
__device__ __half   g_xp[(long)TT * 2 * 8192];     // per-t x images (2 chunks)
__device__ __half   g_W0h[NCTA * 8 * 4096];        // [blk][chunk][32 x 128] images
__device__ __half   g_W0x[NCTA * 2 * 4096];
__device__ __half   g_W1i[NCTA * 8 * 4096];
__device__ __half   g_W1h[NCTA * 8 * 4096];
__device__ __half   g_Wlp[8 * 8 * 4096];           // [colblk][chunk][32 x 128]
__device__ unsigned g_cnt[256];

// ---------------- helpers ----------------
__device__ __forceinline__ float sigm(float v) { return 1.f / (1.f + __expf(-v)); }

__device__ __forceinline__ int kpos16(int k) {     // quad packing within 16-group
    int q = k >> 1, b = k & 1;
    return ((q & 3) << 2) | ((q >> 2) << 1) | b;
}
// image half-offset within a row for (row, kloc in [0,128))
__device__ __forceinline__ int img_off(int row, int kloc) {
    int kpl = (kloc & ~15) + kpos16(kloc & 15);
    return kpl ^ ((row & 7) << 4);
}

__device__ __forceinline__ uint32_t smem_u32(const void* p) {
    uint32_t a;
    asm("{ .reg .u64 t; cvta.to.shared.u64 t, %1; cvt.u32.u64 %0, t; }" : "=r"(a) : "l"(p));
    return a;
}
#define MB_INIT(a, c)  asm volatile("mbarrier.init.shared.b64 [%0], %1;" :: "r"(a), "r"(c) : "memory")
#define MB_EXPECT(a,b) asm volatile("mbarrier.arrive.expect_tx.shared.b64 _, [%0], %1;" :: "r"(a), "r"(b) : "memory")
__device__ __forceinline__ void mb_wait(uint32_t mbar, unsigned parity) {
    asm volatile(
        "{\n\t.reg .pred P1;\n\t"
        "LW_%=:\n\t"
        "mbarrier.try_wait.parity.acquire.cta.shared::cta.b64 P1, [%0], %1, 0x989680;\n\t"
        "@P1 bra.uni LD_%=;\n\t"
        "bra.uni LW_%=;\n\t"
        "LD_%=:\n\t}"
        :: "r"(mbar), "r"(parity) : "memory");
}
__device__ __forceinline__ void bulk_cp(uint32_t dst, const void* src, unsigned bytes, uint32_t mbar) {
    asm volatile(
        "cp.async.bulk.shared::cluster.global.mbarrier::complete_tx::bytes [%0], [%1], %2, [%3];"
        :: "r"(dst), "l"(src), "r"(bytes), "r"(mbar) : "memory");
}
// Issue fills for one chunk into stage s (thread 0 only).
__device__ __forceinline__ void issue(uint32_t sbase, uint32_t mb0, int s,
                                      const __half* A, const __half* B1, const __half* B2) {
    uint32_t mb = mb0 + s * 8;
    uint32_t st = sbase + s * (STGH * 2);
    MB_EXPECT(mb, B2 ? 32768u : 24576u);
    bulk_cp(st, A, 16384u, mb);
    bulk_cp(st + 16384, B1, 8192u, mb);
    if (B2) bulk_cp(st + 24576, B2, 8192u, mb);
}

__device__ __forceinline__ unsigned ld_acq(const unsigned* p) {
    unsigned v;
    asm volatile("ld.acquire.gpu.global.u32 %0, [%1];" : "=r"(v) : "l"(p) : "memory");
    return v;
}
__device__ __forceinline__ void grid_bar(unsigned target) {
    __syncthreads();
    if (threadIdx.x == 0) {
        __threadfence();
        atomicAdd(&g_cnt[(blockIdx.x & 7) << 5], 1u);
        unsigned s;
        do {
            s = 0;
#pragma unroll
            for (int i = 0; i < 8; i++) s += ld_acq(&g_cnt[i << 5]);
        } while (s < target);
    }
    __syncthreads();
}

__device__ __forceinline__ void hmma(float* c, uint32_t a0, uint32_t a1, uint32_t a2,
                                     uint32_t a3, uint32_t b0, uint32_t b1) {
    asm volatile(
        "mma.sync.aligned.m16n8k16.row.col.f32.f16.f16.f32 "
        "{%0,%1,%2,%3}, {%4,%5,%6,%7}, {%8,%9}, {%0,%1,%2,%3};"
        : "+f"(c[0]), "+f"(c[1]), "+f"(c[2]), "+f"(c[3])
        : "r"(a0), "r"(a1), "r"(a2), "r"(a3), "r"(b0), "r"(b1));
}

// Warp m16n16 x k128 against one B image tile (rows of 128 halfs, XOR-swizzled).
__device__ __forceinline__ void mma_one(const __half* A, const __half* B,
                                        float cacc[2][4], int mrow, int nw, int l4, int lq) {
#pragma unroll
    for (int g = 0; g < 8; g++) {
        int off = (g * 16 + 4 * lq) ^ (l4 << 4);
        uint2 va  = *(const uint2*)&A[(mrow + l4) * 128 + off];
        uint2 vb2 = *(const uint2*)&A[(mrow + 8 + l4) * 128 + off];
#pragma unroll
        for (int nt = 0; nt < 2; nt++) {
            uint2 vb = *(const uint2*)&B[(nw + nt * 8 + l4) * 128 + off];
            hmma(&cacc[nt][0], va.x, vb2.x, va.y, vb2.y, vb.x, vb.y);
        }
    }
}
// Same, two B tiles sharing A fragments.
__device__ __forceinline__ void mma_dual(const __half* A, const __half* B1, const __half* B2,
                                         float cB[2][4], float cA[2][4],
                                         int mrow, int nw, int l4, int lq) {
#pragma unroll
    for (int g = 0; g < 8; g++) {
        int off = (g * 16 + 4 * lq) ^ (l4 << 4);
        uint2 va  = *(const uint2*)&A[(mrow + l4) * 128 + off];
        uint2 vb2 = *(const uint2*)&A[(mrow + 8 + l4) * 128 + off];
#pragma unroll
        for (int nt = 0; nt < 2; nt++) {
            uint2 vb = *(const uint2*)&B1[(nw + nt * 8 + l4) * 128 + off];
            hmma(&cB[nt][0], va.x, vb2.x, va.y, vb2.y, vb.x, vb.y);
        }
#pragma unroll
        for (int nt = 0; nt < 2; nt++) {
            uint2 vb = *(const uint2*)&B2[(nw + nt * 8 + l4) * 128 + off];
            hmma(&cA[nt][0], va.x, vb2.x, va.y, vb2.y, vb.x, vb.y);
        }
    }
}

__device__ __forceinline__ void gather(float (*gs)[33], float cacc[2][4],
                                       int mrow, int nw, int l4, int lq) {
#pragma unroll
    for (int nt = 0; nt < 2; nt++) {
        int n0 = nw + nt * 8;
        gs[mrow + l4][n0 + 2 * lq]         = cacc[nt][0];
        gs[mrow + l4][n0 + 2 * lq + 1]     = cacc[nt][1];
        gs[mrow + 8 + l4][n0 + 2 * lq]     = cacc[nt][2];
        gs[mrow + 8 + l4][n0 + 2 * lq + 1] = cacc[nt][3];
    }
}

// LSTM cell: writes h into chunk-image layout. dst/hist are image bases.
__device__ __forceinline__ void cell_pass(const float (*gs)[33], const float* bs,
                                          float (*cc)[8], __half* dst, __half* hist,
                                          int d0, int tid) {
    int ch = d0 >> 7, dl = d0 & 127;
#pragma unroll
    for (int s = 0; s < 2; s++) {
        int idx = tid * 2 + s, r = idx >> 3, j = idx & 7;
        float gi = gs[r][j]      + bs[j];
        float gf = gs[r][8 + j]  + bs[8 + j];
        float gg = gs[r][16 + j] + bs[16 + j];
        float go = gs[r][24 + j] + bs[24 + j];
        float c = sigm(gf) * cc[r][j] + sigm(gi) * tanhf(gg);
        cc[r][j] = c;
        __half h = __float2half_rn(sigm(go) * tanhf(c));
        long off = (long)ch * 8192 + r * 128 + img_off(r, dl + j);
        dst[off] = h;
        if (hist) hist[off] = h;
    }
}

// ---------------- init / pack kernels ----------------
__global__ void init_kernel(const float* __restrict__ z) {
    int i = blockIdx.x * blockDim.x + threadIdx.x;  // over BB*HH
    int b = i >> 10, k = i & 1023;
    int idx = (k >> 7) * 8192 + b * 128 + img_off(b, k & 127);
    __half v = __float2half_rn(z[i]);
    g_h0p[0][idx] = v;
    g_h1p[0][idx] = v;
    if (i < 256) g_cnt[i] = 0u;
}

// Gate-scatter weights -> images. src row = (c>>3)*1024 + blk*8 + (c&7).
__global__ void pack_w(const float* __restrict__ src, __half* __restrict__ dst, int K) {
    int nch = K >> 7;
    long total = (long)NCTA * 32 * K;
    for (long i = blockIdx.x * (long)blockDim.x + threadIdx.x; i < total;
         i += (long)gridDim.x * blockDim.x) {
        int k = (int)(i % K);
        long j = i / K;
        int c = (int)(j & 31);
        int blk = (int)(j >> 5);
        int row = ((c >> 3) << 10) + (blk << 3) + (c & 7);
        long di = ((long)(blk * nch + (k >> 7)) * 32 + c) * 128 + img_off(c, k & 127);
        dst[di] = __float2half_rn(src[(long)row * K + k]);
    }
}
// Plain weights (out proj): src row = blk*32 + c.
__global__ void pack_wl(const float* __restrict__ src, __half* __restrict__ dst) {
    long total = (long)8 * 32 * HH;
    for (long i = blockIdx.x * (long)blockDim.x + threadIdx.x; i < total;
         i += (long)gridDim.x * blockDim.x) {
        int k = (int)(i % HH);
        long j = i / HH;
        int c = (int)(j & 31);
        int blk = (int)(j >> 5);
        long di = ((long)(blk * 8 + (k >> 7)) * 32 + c) * 128 + img_off(c, k & 127);
        dst[di] = __float2half_rn(src[(long)(blk * 32 + c) * HH + k]);
    }
}
__global__ void pack_x(const float* __restrict__ x) {
    long total = (long)TT * BB * IND;
    for (long i = blockIdx.x * (long)blockDim.x + threadIdx.x; i < total;
         i += (long)gridDim.x * blockDim.x) {
        int k = (int)(i % IND);
        int b = (int)((i / IND) & 63);
        int t = (int)(i / (IND * 64));
        long di = (long)t * 16384 + (k >> 7) * 8192 + b * 128 + img_off(b, k & 127);
        g_xp[di] = __float2half_rn(x[((long)b * TT + t) * IND + k]);
    }
}

// ---------------- main persistent kernel ----------------
__global__ __launch_bounds__(256) void lstm_persist(
    const float* __restrict__ bih0, const float* __restrict__ bhh0,
    const float* __restrict__ bih1, const float* __restrict__ bhh1)
{
    extern __shared__ __align__(16) unsigned char smraw[];
    __half* SMh = (__half*)smraw;
    uint32_t sbase = smem_u32(smraw);
    uint32_t mb0 = sbase + MBOFF;
    float* fext  = (float*)(smraw + MBOFF + 64);
    float* bsum0 = fext;
    float* bsum1 = fext + 32;
    float (*cc0)[8] = (float(*)[8])(fext + 64);
    float (*cc1)[8] = cc0 + 64;
    float (*gsB)[33] = (float(*)[33])smraw;              // alias stage 0
    float (*gsA)[33] = (float(*)[33])(smraw + STGH * 2); // alias stage 1

    int tid = threadIdx.x, lane = tid & 31, w = tid >> 5;
    int mrow = (w & 3) * 16, nw = (w >> 2) * 16;
    int l4 = lane >> 2, lq = lane & 3;
    int blk = blockIdx.x, d0 = blk * 8;

    const __half* W0h = g_W0h + (long)blk * 8 * 4096;
    const __half* W0x = g_W0x + (long)blk * 2 * 4096;
    const __half* W1i = g_W1i + (long)blk * 8 * 4096;
    const __half* W1h = g_W1h + (long)blk * 8 * 4096;

    if (tid == 0)
        for (int s = 0; s < 3; s++) MB_INIT(mb0 + s * 8, 1);
    if (tid < 32) {
        int g = tid >> 3, j = tid & 7, n = (g << 10) + d0 + j;
        bsum0[tid] = bih0[n] + bhh0[n];
        bsum1[tid] = bih1[n] + bhh1[n];
    }
    {
        int i0 = tid * 2;
        ((float*)cc0)[i0] = 0.f; ((float*)cc0)[i0 + 1] = 0.f;
        ((float*)cc1)[i0] = 0.f; ((float*)cc1)[i0 + 1] = 0.f;
    }
    __syncthreads();

    long cc = 0;   // consumed-chunk counter (all threads)

    // ---- Prologue: A(0) = z @ W0h ----
    {
        float accA[2][4] = {};
        const __half* A0 = g_h0p[0];
        if (tid == 0) {
            issue(sbase, mb0, (int)(cc % 3), A0, W0h, (const __half*)0);
            issue(sbase, mb0, (int)((cc + 1) % 3), A0 + 8192, W0h + 4096, (const __half*)0);
        }
        for (int i = 0; i < 8; i++) {
            if (tid == 0 && i + 2 < 8)
                issue(sbase, mb0, (int)((cc + 2) % 3), A0 + (i + 2) * 8192,
                      W0h + (i + 2) * 4096, (const __half*)0);
            int s = (int)(cc % 3);
            mb_wait(mb0 + s * 8, (unsigned)((cc / 3) & 1));
            const __half* S = SMh + s * STGH;
            mma_one(S, S + 8192, accA, mrow, nw, l4, lq);
            __syncthreads();
            cc++;
        }
        gather(gsA, accA, mrow, nw, l4, lq);
        __syncthreads();
        cell_pass(gsA, bsum0, cc0, g_h0p[1], (__half*)0, d0, tid);
        grid_bar(NCTA);
    }

    // ---- Main loop: phase t = { B(t), A(t+1) }, one barrier per step ----
    for (int t = 0; t < TT; t++) {
        bool doA = (t + 1 < TT);
        const __half* h0new = g_h0p[(t + 1) & 1];
        const __half* h1old = g_h1p[t & 1];
        const __half* xt    = g_xp + (long)t * 16384;
        int NCH = doA ? 18 : 16;

        float accA[2][4] = {}, accB[2][4] = {};

        if (tid == 0) {
            issue(sbase, mb0, (int)(cc % 3), h0new, W1i, doA ? W0h : (const __half*)0);
            issue(sbase, mb0, (int)((cc + 1) % 3), h0new + 8192, W1i + 4096,
                  doA ? W0h + 4096 : (const __half*)0);
        }
        for (int i = 0; i < NCH; i++) {
            int ip = i + 2;
            if (tid == 0 && ip < NCH) {
                const __half *A, *B1, *B2 = (const __half*)0;
                if (ip < 8) {
                    A = h0new + ip * 8192; B1 = W1i + ip * 4096;
                    if (doA) B2 = W0h + ip * 4096;
                } else if (ip < 16) {
                    A = h1old + (ip - 8) * 8192; B1 = W1h + (ip - 8) * 4096;
                } else {
                    A = xt + (ip - 16) * 8192; B1 = W0x + (ip - 16) * 4096;
                }
                issue(sbase, mb0, (int)((cc + 2) % 3), A, B1, B2);
            }
            int s = (int)(cc % 3);
            mb_wait(mb0 + s * 8, (unsigned)((cc / 3) & 1));
            const __half* S = SMh + s * STGH;
            if (i < 8) {
                if (doA) mma_dual(S, S + 8192, S + 12288, accB, accA, mrow, nw, l4, lq);
                else     mma_one(S, S + 8192, accB, mrow, nw, l4, lq);
            } else if (i < 16) {
                mma_one(S, S + 8192, accB, mrow, nw, l4, lq);
            } else {
                mma_one(S, S + 8192, accA, mrow, nw, l4, lq);
            }
            __syncthreads();
            cc++;
        }

        gather(gsB, accB, mrow, nw, l4, lq);
        if (doA) gather(gsA, accA, mrow, nw, l4, lq);
        __syncthreads();
        cell_pass(gsB, bsum1, cc1, g_h1p[(t + 1) & 1],
                  g_h1all + (long)t * 65536, d0, tid);
        if (doA) {
            cell_pass(gsA, bsum0, cc0, g_h0p[t & 1], (__half*)0, d0, tid);
            grid_bar((unsigned)(t + 2) * NCTA);
        }
    }
}

// ---------------- deferred output projection ----------------
__global__ __launch_bounds__(256) void out_kernel(
    const float* __restrict__ blin, float* __restrict__ out)
{
    extern __shared__ __align__(16) unsigned char smraw[];
    __half* SMh = (__half*)smraw;
    uint32_t sbase = smem_u32(smraw);
    uint32_t mb0 = sbase + MBOFF;
    float (*gs)[33] = (float(*)[33])smraw;

    int tid = threadIdx.x, lane = tid & 31, w = tid >> 5;
    int mrow = (w & 3) * 16, nw = (w >> 2) * 16;
    int l4 = lane >> 2, lq = lane & 3;
    int t = blockIdx.x;                       // 64-row block == one timestep
    int cb = blockIdx.y;

    const __half* A  = g_h1all + (long)t * 65536;
    const __half* Wb = g_Wlp + (long)cb * 8 * 4096;
    float acc[2][4] = {};

    if (tid == 0)
        for (int s = 0; s < 3; s++) MB_INIT(mb0 + s * 8, 1);
    __syncthreads();

    if (tid == 0) {
        issue(sbase, mb0, 0, A, Wb, (const __half*)0);
        issue(sbase, mb0, 1, A + 8192, Wb + 4096, (const __half*)0);
    }
    long cc = 0;
    for (int i = 0; i < 8; i++) {
        if (tid == 0 && i + 2 < 8)
            issue(sbase, mb0, (int)((cc + 2) % 3), A + (i + 2) * 8192,
                  Wb + (i + 2) * 4096, (const __half*)0);
        int s = (int)(cc % 3);
        mb_wait(mb0 + s * 8, (unsigned)((cc / 3) & 1));
        const __half* S = SMh + s * STGH;
        mma_one(S, S + 8192, acc, mrow, nw, l4, lq);
        __syncthreads();
        cc++;
    }

    gather(gs, acc, mrow, nw, l4, lq);
    __syncthreads();

#pragma unroll
    for (int s = 0; s < 8; s++) {
        int idx = tid + s * 256;
        int b = idx >> 5, c = idx & 31;
        int o = cb * 32 + c;
        out[(long)b * (TT * OUTD) + t * OUTD + o] = gs[b][c] + blin[o];
    }
}

// ---------------- host launcher ----------------
extern "C" void kernel_launch(void* const* d_in, const int* in_sizes, int n_in,
                              void* d_out, int out_size)
{
    const float* z    = (const float*)d_in[0];
    const float* x    = (const float*)d_in[1];
    const float* Wih0 = (const float*)d_in[2];
    const float* Whh0 = (const float*)d_in[3];
    const float* bih0 = (const float*)d_in[4];
    const float* bhh0 = (const float*)d_in[5];
    const float* Wih1 = (const float*)d_in[6];
    const float* Whh1 = (const float*)d_in[7];
    const float* bih1 = (const float*)d_in[8];
    const float* bhh1 = (const float*)d_in[9];
    const float* Wlin = (const float*)d_in[10];
    const float* blin = (const float*)d_in[11];
    float* out = (float*)d_out;

    const int SMEM_MAIN = MBOFF + 64 + (64 + 1024) * 4;   // 102,720
    cudaFuncSetAttribute(lstm_persist, cudaFuncAttributeMaxDynamicSharedMemorySize, SMEM_MAIN);
    cudaFuncSetAttribute(out_kernel,   cudaFuncAttributeMaxDynamicSharedMemorySize, SMEM_MAIN);

    __half* dW0h; cudaGetSymbolAddress((void**)&dW0h, g_W0h);
    __half* dW0x; cudaGetSymbolAddress((void**)&dW0x, g_W0x);
    __half* dW1i; cudaGetSymbolAddress((void**)&dW1i, g_W1i);
    __half* dW1h; cudaGetSymbolAddress((void**)&dW1h, g_W1h);
    __half* dWlp; cudaGetSymbolAddress((void**)&dWlp, g_Wlp);

    init_kernel<<<64, 1024>>>(z);
    pack_w<<<2048, 256>>>(Whh0, dW0h, HH);
    pack_w<<<1024, 256>>>(Wih0, dW0x, IND);
    pack_w<<<2048, 256>>>(Wih1, dW1i, HH);
    pack_w<<<2048, 256>>>(Whh1, dW1h, HH);
    pack_wl<<<256, 256>>>(Wlin, dWlp);
    pack_x<<<2048, 256>>>(x);

    lstm_persist<<<NCTA, 256, SMEM_MAIN>>>(bih0, bhh0, bih1, bhh1);
    out_kernel<<<dim3(TT, OUTD / 32), 256, SMEM_MAIN>>>(blin, out);
}

// round 13
// speedup vs baseline: 1.7047x; 1.0819x over previous
#include <cuda_runtime.h>
#include <cuda_fp16.h>
#include <stdint.h>
#include <math.h>

#define BB   64
#define TT   512
#define IND  256
#define OUTD 256
#define HH   1024
#define NCTA 128
#define STGB  65536            // bytes/stage: A 32KB | B1 16KB | B2 16KB
#define MBOFF (3 * STGB)       // 196608

// ---------------- persistent device state (chunk-image layouts, as R11) ----------------
__device__ __half   g_h0p[2][8 * 8192];
__device__ __half   g_h1p[2][8 * 8192];
__device__ __half   g_h1all[(long)TT * 8 * 8192];
__device__ __half   g_xp[(long)TT * 2 * 8192];
__device__ __half   g_W0h[NCTA * 8 * 4096];
__device__ __half   g_W0x[NCTA * 2 * 4096];
__device__ __half   g_W1i[NCTA * 8 * 4096];
__device__ __half   g_W1h[NCTA * 8 * 4096];
__device__ __half   g_Wlp[8 * 8 * 4096];
__device__ unsigned g_cnt[256];

// ---------------- helpers ----------------
__device__ __forceinline__ float sigm(float v) { return 1.f / (1.f + __expf(-v)); }

__device__ __forceinline__ int kpos16(int k) {
    int q = k >> 1, b = k & 1;
    return ((q & 3) << 2) | ((q >> 2) << 1) | b;
}
__device__ __forceinline__ int img_off(int row, int kloc) {
    int kpl = (kloc & ~15) + kpos16(kloc & 15);
    return kpl ^ ((row & 7) << 4);
}
__device__ __forceinline__ uint32_t smem_u32(const void* p) {
    uint32_t a;
    asm("{ .reg .u64 t; cvta.to.shared.u64 t, %1; cvt.u32.u64 %0, t; }" : "=r"(a) : "l"(p));
    return a;
}
#define MB_INIT(a, c)  asm volatile("mbarrier.init.shared.b64 [%0], %1;" :: "r"(a), "r"(c) : "memory")
#define MB_EXPECT(a,b) asm volatile("mbarrier.arrive.expect_tx.shared.b64 _, [%0], %1;" :: "r"(a), "r"(b) : "memory")
__device__ __forceinline__ void mb_wait(uint32_t m, unsigned p) {
    asm volatile(
        "{\n\t.reg .pred P1;\n\tLW_%=:\n\t"
        "mbarrier.try_wait.parity.acquire.cta.shared::cta.b64 P1, [%0], %1, 0x989680;\n\t"
        "@P1 bra.uni LD_%=;\n\tbra.uni LW_%=;\n\tLD_%=:\n\t}" :: "r"(m), "r"(p) : "memory");
}
__device__ __forceinline__ void bulk_cp(uint32_t d, const void* s, unsigned b, uint32_t m) {
    asm volatile("cp.async.bulk.shared::cluster.global.mbarrier::complete_tx::bytes [%0], [%1], %2, [%3];"
                 :: "r"(d), "l"(s), "r"(b), "r"(m) : "memory");
}
// producer: one K=256 superchunk -> stage gF%3 (safety from per-chunk __syncthreads, 2-ahead)
__device__ __forceinline__ void produce(uint32_t sb, uint32_t mb0, long gF,
                                        const __half* A, const __half* B1, const __half* B2) {
    int s = (int)(gF % 3);
    uint32_t st = sb + s * STGB, fb = mb0 + s * 8;
    MB_EXPECT(fb, B2 ? 65536u : 49152u);
    bulk_cp(st, A, 32768u, fb);
    bulk_cp(st + 32768, B1, 16384u, fb);
    if (B2) bulk_cp(st + 49152, B2, 16384u, fb);
}
__device__ __forceinline__ unsigned ld_acq(const unsigned* p) {
    unsigned v;
    asm volatile("ld.acquire.gpu.global.u32 %0, [%1];" : "=r"(v) : "l"(p) : "memory");
    return v;
}
__device__ __forceinline__ void grid_bar(unsigned target) {
    __syncthreads();
    if (threadIdx.x == 0) {
        __threadfence();
        atomicAdd(&g_cnt[(blockIdx.x & 7) << 5], 1u);
        unsigned s;
        do { s = 0;
#pragma unroll
            for (int i = 0; i < 8; i++) s += ld_acq(&g_cnt[i << 5]);
        } while (s < target);
    }
    __syncthreads();
}
__device__ __forceinline__ void hmma(float* c, uint32_t a0, uint32_t a1, uint32_t a2,
                                     uint32_t a3, uint32_t b0, uint32_t b1) {
    asm volatile(
        "mma.sync.aligned.m16n8k16.row.col.f32.f16.f16.f32 "
        "{%0,%1,%2,%3}, {%4,%5,%6,%7}, {%8,%9}, {%0,%1,%2,%3};"
        : "+f"(c[0]), "+f"(c[1]), "+f"(c[2]), "+f"(c[3])
        : "r"(a0), "r"(a1), "r"(a2), "r"(a3), "r"(b0), "r"(b1));
}

// Warp m32 x n16 over its k128 half vs one B tile.
__device__ __forceinline__ void mma_ks1(const __half* A, const __half* B,
                                        float acc[2][2][4], int mrow, int nw, int l4, int lq) {
#pragma unroll
    for (int g = 0; g < 8; g++) {
        int off = (g * 16 + 4 * lq) ^ (l4 << 4);
        uint2 a00 = *(const uint2*)&A[(mrow + l4) * 128 + off];
        uint2 a01 = *(const uint2*)&A[(mrow + 8 + l4) * 128 + off];
        uint2 a10 = *(const uint2*)&A[(mrow + 16 + l4) * 128 + off];
        uint2 a11 = *(const uint2*)&A[(mrow + 24 + l4) * 128 + off];
#pragma unroll
        for (int nt = 0; nt < 2; nt++) {
            uint2 vb = *(const uint2*)&B[(nw + nt * 8 + l4) * 128 + off];
            hmma(&acc[0][nt][0], a00.x, a01.x, a00.y, a01.y, vb.x, vb.y);
            hmma(&acc[1][nt][0], a10.x, a11.x, a10.y, a11.y, vb.x, vb.y);
        }
    }
}
// Same vs two B tiles sharing A fragments.
__device__ __forceinline__ void mma_ks2(const __half* A, const __half* B1, const __half* B2,
                                        float aB[2][2][4], float aA[2][2][4],
                                        int mrow, int nw, int l4, int lq) {
#pragma unroll
    for (int g = 0; g < 8; g++) {
        int off = (g * 16 + 4 * lq) ^ (l4 << 4);
        uint2 a00 = *(const uint2*)&A[(mrow + l4) * 128 + off];
        uint2 a01 = *(const uint2*)&A[(mrow + 8 + l4) * 128 + off];
        uint2 a10 = *(const uint2*)&A[(mrow + 16 + l4) * 128 + off];
        uint2 a11 = *(const uint2*)&A[(mrow + 24 + l4) * 128 + off];
#pragma unroll
        for (int nt = 0; nt < 2; nt++) {
            uint2 vb = *(const uint2*)&B1[(nw + nt * 8 + l4) * 128 + off];
            hmma(&aB[0][nt][0], a00.x, a01.x, a00.y, a01.y, vb.x, vb.y);
            hmma(&aB[1][nt][0], a10.x, a11.x, a10.y, a11.y, vb.x, vb.y);
        }
#pragma unroll
        for (int nt = 0; nt < 2; nt++) {
            uint2 vb = *(const uint2*)&B2[(nw + nt * 8 + l4) * 128 + off];
            hmma(&aA[0][nt][0], a00.x, a01.x, a00.y, a01.y, vb.x, vb.y);
            hmma(&aA[1][nt][0], a10.x, a11.x, a10.y, a11.y, vb.x, vb.y);
        }
    }
}
// Two-phase K-split gather: ks=0 warps write, ks=1 warps add.
__device__ __forceinline__ void gather2(float (*gs)[33], float acc[2][2][4],
                                        int mrow, int nw, int l4, int lq, bool add) {
#pragma unroll
    for (int mb = 0; mb < 2; mb++)
#pragma unroll
        for (int nt = 0; nt < 2; nt++) {
            int c = nw + nt * 8 + 2 * lq;
            int r = mrow + mb * 16 + l4;
            if (add) {
                gs[r][c]     += acc[mb][nt][0]; gs[r][c + 1]     += acc[mb][nt][1];
                gs[r + 8][c] += acc[mb][nt][2]; gs[r + 8][c + 1] += acc[mb][nt][3];
            } else {
                gs[r][c]     = acc[mb][nt][0]; gs[r][c + 1]     = acc[mb][nt][1];
                gs[r + 8][c] = acc[mb][nt][2]; gs[r + 8][c + 1] = acc[mb][nt][3];
            }
        }
}
// LSTM cell over the CTA's 8 dims x 64 rows (image-layout writes).
__device__ __forceinline__ void cell_pass(const float (*gs)[33], const float* bs,
                                          float (*cc)[8], __half* dst, __half* hist,
                                          int d0, int tid) {
    int ch = d0 >> 7, dl = d0 & 127;
#pragma unroll
    for (int s = 0; s < 2; s++) {
        int idx = tid * 2 + s, r = idx >> 3, j = idx & 7;
        float gi = gs[r][j]      + bs[j];
        float gf = gs[r][8 + j]  + bs[8 + j];
        float gg = gs[r][16 + j] + bs[16 + j];
        float go = gs[r][24 + j] + bs[24 + j];
        float c = sigm(gf) * cc[r][j] + sigm(gi) * tanhf(gg);
        cc[r][j] = c;
        __half h = __float2half_rn(sigm(go) * tanhf(c));
        long off = (long)ch * 8192 + r * 128 + img_off(r, dl + j);
        dst[off] = h;
        if (hist) hist[off] = h;
    }
}

// ---------------- init / pack kernels (R11 verbatim) ----------------
__global__ void init_kernel(const float* __restrict__ z) {
    int i = blockIdx.x * blockDim.x + threadIdx.x;
    int b = i >> 10, k = i & 1023;
    int idx = (k >> 7) * 8192 + b * 128 + img_off(b, k & 127);
    __half v = __float2half_rn(z[i]);
    g_h0p[0][idx] = v;
    g_h1p[0][idx] = v;
    if (i < 256) g_cnt[i] = 0u;
}
__global__ void pack_w(const float* __restrict__ src, __half* __restrict__ dst, int K) {
    int nch = K >> 7;
    long total = (long)NCTA * 32 * K;
    for (long i = blockIdx.x * (long)blockDim.x + threadIdx.x; i < total;
         i += (long)gridDim.x * blockDim.x) {
        int k = (int)(i % K);
        long j = i / K;
        int c = (int)(j & 31);
        int blk = (int)(j >> 5);
        int row = ((c >> 3) << 10) + (blk << 3) + (c & 7);
        long di = ((long)(blk * nch + (k >> 7)) * 32 + c) * 128 + img_off(c, k & 127);
        dst[di] = __float2half_rn(src[(long)row * K + k]);
    }
}
__global__ void pack_wl(const float* __restrict__ src, __half* __restrict__ dst) {
    long total = (long)8 * 32 * HH;
    for (long i = blockIdx.x * (long)blockDim.x + threadIdx.x; i < total;
         i += (long)gridDim.x * blockDim.x) {
        int k = (int)(i % HH);
        long j = i / HH;
        int c = (int)(j & 31);
        int blk = (int)(j >> 5);
        long di = ((long)(blk * 8 + (k >> 7)) * 32 + c) * 128 + img_off(c, k & 127);
        dst[di] = __float2half_rn(src[(long)(blk * 32 + c) * HH + k]);
    }
}
__global__ void pack_x(const float* __restrict__ x) {
    long total = (long)TT * BB * IND;
    for (long i = blockIdx.x * (long)blockDim.x + threadIdx.x; i < total;
         i += (long)gridDim.x * blockDim.x) {
        int k = (int)(i % IND);
        int b = (int)((i / IND) & 63);
        int t = (int)(i / (IND * 64));
        long di = (long)t * 16384 + (k >> 7) * 8192 + b * 128 + img_off(b, k & 127);
        g_xp[di] = __float2half_rn(x[((long)b * TT + t) * IND + k]);
    }
}

// ---------------- main persistent kernel ----------------
__global__ __launch_bounds__(256) void lstm_persist(
    const float* __restrict__ bih0, const float* __restrict__ bhh0,
    const float* __restrict__ bih1, const float* __restrict__ bhh1)
{
    extern __shared__ __align__(16) unsigned char smraw[];
    __half* SMh = (__half*)smraw;
    uint32_t sbase = smem_u32(smraw);
    uint32_t mb0 = sbase + MBOFF;
    float* fext  = (float*)(smraw + MBOFF + 64);
    float* bsum0 = fext;
    float* bsum1 = fext + 32;
    float (*cc0)[8] = (float(*)[8])(fext + 64);
    float (*cc1)[8] = cc0 + 64;
    float (*gsB)[33] = (float(*)[33])smraw;                  // alias stage 0 (free at epilogue)
    float (*gsA)[33] = (float(*)[33])(smraw + 16384);

    int tid = threadIdx.x, lane = tid & 31, w = tid >> 5;
    int ks = w >> 2;                                         // k-half
    int mrow = ((w >> 1) & 1) * 32, nw = (w & 1) * 16;
    int l4 = lane >> 2, lq = lane & 3;
    int blk = blockIdx.x, d0 = blk * 8;

    const __half* W0h = g_W0h + (long)blk * 8 * 4096;
    const __half* W0x = g_W0x + (long)blk * 2 * 4096;
    const __half* W1i = g_W1i + (long)blk * 8 * 4096;
    const __half* W1h = g_W1h + (long)blk * 8 * 4096;

    if (tid == 0)
        for (int s = 0; s < 3; s++) MB_INIT(mb0 + s * 8, 1);
    if (tid < 32) {
        int g = tid >> 3, j = tid & 7, n = (g << 10) + d0 + j;
        bsum0[tid] = bih0[n] + bhh0[n];
        bsum1[tid] = bih1[n] + bhh1[n];
    }
    {
        int i0 = tid * 2;
        ((float*)cc0)[i0] = 0.f; ((float*)cc0)[i0 + 1] = 0.f;
        ((float*)cc1)[i0] = 0.f; ((float*)cc1)[i0 + 1] = 0.f;
    }
    __syncthreads();

    long cc = 0;

    // ---- Prologue: A(0) = z @ W0h  (4 superchunks) ----
    {
        float accA[2][2][4] = {};
        const __half* A0 = g_h0p[0];
        if (tid == 0) {
            produce(sbase, mb0, cc,     A0,         W0h,        (const __half*)0);
            produce(sbase, mb0, cc + 1, A0 + 16384, W0h + 8192, (const __half*)0);
        }
        for (int i = 0; i < 4; i++) {
            if (tid == 0 && i + 2 < 4)
                produce(sbase, mb0, cc + 2, A0 + (i + 2) * 16384,
                        W0h + (i + 2) * 8192, (const __half*)0);
            int s = (int)(cc % 3);
            mb_wait(mb0 + s * 8, (unsigned)((cc / 3) & 1));
            const __half* S = SMh + (long)s * 32768;
            mma_ks1(S + ks * 8192, S + 16384 + ks * 4096, accA, mrow, nw, l4, lq);
            __syncthreads();
            cc++;
        }
        if (ks == 0) gather2(gsA, accA, mrow, nw, l4, lq, false);
        __syncthreads();
        if (ks == 1) gather2(gsA, accA, mrow, nw, l4, lq, true);
        __syncthreads();
        cell_pass(gsA, bsum0, cc0, g_h0p[1], (__half*)0, d0, tid);
        grid_bar(NCTA);
    }

    // ---- Main loop: phase t = { B(t), A(t+1) }, one barrier per step ----
    for (int t = 0; t < TT; t++) {
        bool doA = (t + 1 < TT);
        const __half* h0new = g_h0p[(t + 1) & 1];
        const __half* h1old = g_h1p[t & 1];
        const __half* xt    = g_xp + (long)t * 16384;
        int NCH = doA ? 9 : 8;

        float accA[2][2][4] = {}, accB[2][2][4] = {};

        if (tid == 0) {
            produce(sbase, mb0, cc,     h0new,         W1i,        doA ? W0h : (const __half*)0);
            produce(sbase, mb0, cc + 1, h0new + 16384, W1i + 8192, doA ? W0h + 8192 : (const __half*)0);
        }
        for (int i = 0; i < NCH; i++) {
            int ip = i + 2;
            if (tid == 0 && ip < NCH) {
                const __half *A, *B1, *B2 = (const __half*)0;
                if (ip < 4) {
                    A = h0new + ip * 16384; B1 = W1i + ip * 8192;
                    if (doA) B2 = W0h + ip * 8192;
                } else if (ip < 8) {
                    A = h1old + (ip - 4) * 16384; B1 = W1h + (ip - 4) * 8192;
                } else {
                    A = xt; B1 = W0x;
                }
                produce(sbase, mb0, cc + 2, A, B1, B2);
            }
            int s = (int)(cc % 3);
            mb_wait(mb0 + s * 8, (unsigned)((cc / 3) & 1));
            const __half* S  = SMh + (long)s * 32768;
            const __half* Ak = S + ks * 8192;
            const __half* B1k = S + 16384 + ks * 4096;
            const __half* B2k = S + 24576 + ks * 4096;
            if (i < 4) {
                if (doA) mma_ks2(Ak, B1k, B2k, accB, accA, mrow, nw, l4, lq);
                else     mma_ks1(Ak, B1k, accB, mrow, nw, l4, lq);
            } else if (i < 8) {
                mma_ks1(Ak, B1k, accB, mrow, nw, l4, lq);
            } else {
                mma_ks1(Ak, B1k, accA, mrow, nw, l4, lq);
            }
            __syncthreads();
            cc++;
        }

        if (ks == 0) {
            gather2(gsB, accB, mrow, nw, l4, lq, false);
            if (doA) gather2(gsA, accA, mrow, nw, l4, lq, false);
        }
        __syncthreads();
        if (ks == 1) {
            gather2(gsB, accB, mrow, nw, l4, lq, true);
            if (doA) gather2(gsA, accA, mrow, nw, l4, lq, true);
        }
        __syncthreads();
        cell_pass(gsB, bsum1, cc1, g_h1p[(t + 1) & 1],
                  g_h1all + (long)t * 65536, d0, tid);
        if (doA) {
            cell_pass(gsA, bsum0, cc0, g_h0p[t & 1], (__half*)0, d0, tid);
            grid_bar((unsigned)(t + 2) * NCTA);
        }
    }
}

// ---------------- deferred output projection ----------------
__global__ __launch_bounds__(256) void out_kernel(
    const float* __restrict__ blin, float* __restrict__ out)
{
    extern __shared__ __align__(16) unsigned char smraw[];
    __half* SMh = (__half*)smraw;
    uint32_t sbase = smem_u32(smraw);
    uint32_t mb0 = sbase + MBOFF;
    float (*gs)[33] = (float(*)[33])smraw;

    int tid = threadIdx.x, lane = tid & 31, w = tid >> 5;
    int ks = w >> 2;
    int mrow = ((w >> 1) & 1) * 32, nw = (w & 1) * 16;
    int l4 = lane >> 2, lq = lane & 3;
    int t = blockIdx.x, cb = blockIdx.y;

    const __half* A  = g_h1all + (long)t * 65536;
    const __half* Wb = g_Wlp + (long)cb * 8 * 4096;
    float acc[2][2][4] = {};

    if (tid == 0)
        for (int s = 0; s < 3; s++) MB_INIT(mb0 + s * 8, 1);
    __syncthreads();

    if (tid == 0) {
        produce(sbase, mb0, 0, A,         Wb,        (const __half*)0);
        produce(sbase, mb0, 1, A + 16384, Wb + 8192, (const __half*)0);
    }
    long cc = 0;
    for (int i = 0; i < 4; i++) {
        if (tid == 0 && i + 2 < 4)
            produce(sbase, mb0, cc + 2, A + (i + 2) * 16384,
                    Wb + (i + 2) * 8192, (const __half*)0);
        int s = (int)(cc % 3);
        mb_wait(mb0 + s * 8, (unsigned)((cc / 3) & 1));
        const __half* S = SMh + (long)s * 32768;
        mma_ks1(S + ks * 8192, S + 16384 + ks * 4096, acc, mrow, nw, l4, lq);
        __syncthreads();
        cc++;
    }

    if (ks == 0) gather2(gs, acc, mrow, nw, l4, lq, false);
    __syncthreads();
    if (ks == 1) gather2(gs, acc, mrow, nw, l4, lq, true);
    __syncthreads();

#pragma unroll
    for (int s = 0; s < 8; s++) {
        int idx = tid + s * 256;
        int b = idx >> 5, c = idx & 31;
        int o = cb * 32 + c;
        out[(long)b * (TT * OUTD) + t * OUTD + o] = gs[b][c] + blin[o];
    }
}

// ---------------- host launcher ----------------
extern "C" void kernel_launch(void* const* d_in, const int* in_sizes, int n_in,
                              void* d_out, int out_size)
{
    const float* z    = (const float*)d_in[0];
    const float* x    = (const float*)d_in[1];
    const float* Wih0 = (const float*)d_in[2];
    const float* Whh0 = (const float*)d_in[3];
    const float* bih0 = (const float*)d_in[4];
    const float* bhh0 = (const float*)d_in[5];
    const float* Wih1 = (const float*)d_in[6];
    const float* Whh1 = (const float*)d_in[7];
    const float* bih1 = (const float*)d_in[8];
    const float* bhh1 = (const float*)d_in[9];
    const float* Wlin = (const float*)d_in[10];
    const float* blin = (const float*)d_in[11];
    float* out = (float*)d_out;

    const int SMEM = MBOFF + 64 + (64 + 1024) * 4;   // 201,024 B
    cudaFuncSetAttribute(lstm_persist, cudaFuncAttributeMaxDynamicSharedMemorySize, SMEM);
    cudaFuncSetAttribute(out_kernel,   cudaFuncAttributeMaxDynamicSharedMemorySize, SMEM);

    __half* dW0h; cudaGetSymbolAddress((void**)&dW0h, g_W0h);
    __half* dW0x; cudaGetSymbolAddress((void**)&dW0x, g_W0x);
    __half* dW1i; cudaGetSymbolAddress((void**)&dW1i, g_W1i);
    __half* dW1h; cudaGetSymbolAddress((void**)&dW1h, g_W1h);
    __half* dWlp; cudaGetSymbolAddress((void**)&dWlp, g_Wlp);

    init_kernel<<<64, 1024>>>(z);
    pack_w<<<2048, 256>>>(Whh0, dW0h, HH);
    pack_w<<<1024, 256>>>(Wih0, dW0x, IND);
    pack_w<<<2048, 256>>>(Wih1, dW1i, HH);
    pack_w<<<2048, 256>>>(Whh1, dW1h, HH);
    pack_wl<<<256, 256>>>(Wlin, dWlp);
    pack_x<<<2048, 256>>>(x);

    lstm_persist<<<NCTA, 256, SMEM>>>(bih0, bhh0, bih1, bhh1);
    out_kernel<<<dim3(TT, OUTD / 32), 256, SMEM>>>(blin, out);
}

// round 14
// speedup vs baseline: 1.7190x; 1.0083x over previous
#include <cuda_runtime.h>
#include <cuda_fp16.h>
#include <stdint.h>
#include <math.h>

#define BB   64
#define TT   512
#define IND  256
#define OUTD 256
#define HH   1024
#define NCTA 128
#define STGB   65536                 // stage: A 32KB | B1 16KB | B2 16KB
#define GOFF   (3 * STGB)            // 196608: 4 gather buffers (64x33 f32 each)
#define MBOFF2 (GOFF + 4 * 8448)     // 230400: full[3]@0,8,16  cons[3]@24,32,40
#define BIASOFF (MBOFF2 + 64)        // 230464: bs1[32], bs0[32]
#define SMEM_TOT (BIASOFF + 256)     // 230720

// ---------------- persistent device state (chunk-image layouts, as R13) ----------------
__device__ __half   g_h0p[2][8 * 8192];
__device__ __half   g_h1p[2][8 * 8192];
__device__ __half   g_h1all[(long)TT * 8 * 8192];
__device__ __half   g_xp[(long)TT * 2 * 8192];
__device__ __half   g_W0h[NCTA * 8 * 4096];
__device__ __half   g_W0x[NCTA * 2 * 4096];
__device__ __half   g_W1i[NCTA * 8 * 4096];
__device__ __half   g_W1h[NCTA * 8 * 4096];
__device__ __half   g_Wlp[8 * 8 * 4096];
__device__ unsigned g_cnt[256];

// ---------------- helpers ----------------
__device__ __forceinline__ float sigm(float v) {
    return __fdividef(1.f, 1.f + __expf(-v));
}
__device__ __forceinline__ float ftanh(float x) {
    float e = __expf(-2.f * x);
    return __fdividef(1.f - e, 1.f + e);
}
__device__ __forceinline__ int kpos16(int k) {
    int q = k >> 1, b = k & 1;
    return ((q & 3) << 2) | ((q >> 2) << 1) | b;
}
__device__ __forceinline__ int img_off(int row, int kloc) {
    int kpl = (kloc & ~15) + kpos16(kloc & 15);
    return kpl ^ ((row & 7) << 4);
}
__device__ __forceinline__ uint32_t smem_u32(const void* p) {
    uint32_t a;
    asm("{ .reg .u64 t; cvta.to.shared.u64 t, %1; cvt.u32.u64 %0, t; }" : "=r"(a) : "l"(p));
    return a;
}
#define MB_INIT(a, c)  asm volatile("mbarrier.init.shared.b64 [%0], %1;" :: "r"(a), "r"(c) : "memory")
#define MB_EXPECT(a,b) asm volatile("mbarrier.arrive.expect_tx.shared.b64 _, [%0], %1;" :: "r"(a), "r"(b) : "memory")
#define MB_ARRIVE(a)   asm volatile("mbarrier.arrive.shared.b64 _, [%0];" :: "r"(a) : "memory")
__device__ __forceinline__ void mb_wait(uint32_t m, unsigned p) {
    asm volatile(
        "{\n\t.reg .pred P1;\n\tLW_%=:\n\t"
        "mbarrier.try_wait.parity.acquire.cta.shared::cta.b64 P1, [%0], %1, 0x989680;\n\t"
        "@P1 bra.uni LD_%=;\n\tbra.uni LW_%=;\n\tLD_%=:\n\t}" :: "r"(m), "r"(p) : "memory");
}
__device__ __forceinline__ void bulk_cp(uint32_t d, const void* s, unsigned b, uint32_t m) {
    asm volatile("cp.async.bulk.shared::cluster.global.mbarrier::complete_tx::bytes [%0], [%1], %2, [%3];"
                 :: "r"(d), "l"(s), "r"(b), "r"(m) : "memory");
}
// producer with consumed-backpressure (main kernel)
__device__ __forceinline__ void produce_g(uint32_t sb, long g, const __half* A,
                                          const __half* B1, const __half* B2) {
    int s = (int)(g % 3);
    uint32_t mb = sb + MBOFF2;
    if (g >= 3) mb_wait(mb + 24 + s * 8, (unsigned)(((g / 3) - 1) & 1));
    uint32_t st = sb + s * STGB, fb = mb + s * 8;
    MB_EXPECT(fb, B2 ? 65536u : 49152u);
    bulk_cp(st, A, 32768u, fb);
    bulk_cp(st + 32768, B1, 16384u, fb);
    if (B2) bulk_cp(st + 49152, B2, 16384u, fb);
}
// producer for out_kernel (syncthreads discipline, as R13)
__device__ __forceinline__ void produce_o(uint32_t sb, long g, const __half* A, const __half* B1) {
    int s = (int)(g % 3);
    uint32_t st = sb + s * STGB, fb = sb + MBOFF2 + s * 8;
    MB_EXPECT(fb, 49152u);
    bulk_cp(st, A, 32768u, fb);
    bulk_cp(st + 32768, B1, 16384u, fb);
}
__device__ __forceinline__ unsigned ld_acq(const unsigned* p) {
    unsigned v;
    asm volatile("ld.acquire.gpu.global.u32 %0, [%1];" : "=r"(v) : "l"(p) : "memory");
    return v;
}
__device__ __forceinline__ void grid_bar(unsigned target) {
    __syncthreads();
    if (threadIdx.x == 0) {
        __threadfence();
        atomicAdd(&g_cnt[(blockIdx.x & 7) << 5], 1u);
        unsigned s;
        do { s = 0;
#pragma unroll
            for (int i = 0; i < 8; i++) s += ld_acq(&g_cnt[i << 5]);
        } while (s < target);
    }
    __syncthreads();
}
__device__ __forceinline__ void hmma(float* c, uint32_t a0, uint32_t a1, uint32_t a2,
                                     uint32_t a3, uint32_t b0, uint32_t b1) {
    asm volatile(
        "mma.sync.aligned.m16n8k16.row.col.f32.f16.f16.f32 "
        "{%0,%1,%2,%3}, {%4,%5,%6,%7}, {%8,%9}, {%0,%1,%2,%3};"
        : "+f"(c[0]), "+f"(c[1]), "+f"(c[2]), "+f"(c[3])
        : "r"(a0), "r"(a1), "r"(a2), "r"(a3), "r"(b0), "r"(b1));
}
// Warp m32 x n16 over its k128 half vs one B tile.
__device__ __forceinline__ void mma_ks1(const __half* A, const __half* B,
                                        float acc[2][2][4], int mrow, int nw, int l4, int lq) {
#pragma unroll
    for (int g = 0; g < 8; g++) {
        int off = (g * 16 + 4 * lq) ^ (l4 << 4);
        uint2 a00 = *(const uint2*)&A[(mrow + l4) * 128 + off];
        uint2 a01 = *(const uint2*)&A[(mrow + 8 + l4) * 128 + off];
        uint2 a10 = *(const uint2*)&A[(mrow + 16 + l4) * 128 + off];
        uint2 a11 = *(const uint2*)&A[(mrow + 24 + l4) * 128 + off];
#pragma unroll
        for (int nt = 0; nt < 2; nt++) {
            uint2 vb = *(const uint2*)&B[(nw + nt * 8 + l4) * 128 + off];
            hmma(&acc[0][nt][0], a00.x, a01.x, a00.y, a01.y, vb.x, vb.y);
            hmma(&acc[1][nt][0], a10.x, a11.x, a10.y, a11.y, vb.x, vb.y);
        }
    }
}
// Same vs two B tiles sharing A fragments.
__device__ __forceinline__ void mma_ks2(const __half* A, const __half* B1, const __half* B2,
                                        float aB[2][2][4], float aA[2][2][4],
                                        int mrow, int nw, int l4, int lq) {
#pragma unroll
    for (int g = 0; g < 8; g++) {
        int off = (g * 16 + 4 * lq) ^ (l4 << 4);
        uint2 a00 = *(const uint2*)&A[(mrow + l4) * 128 + off];
        uint2 a01 = *(const uint2*)&A[(mrow + 8 + l4) * 128 + off];
        uint2 a10 = *(const uint2*)&A[(mrow + 16 + l4) * 128 + off];
        uint2 a11 = *(const uint2*)&A[(mrow + 24 + l4) * 128 + off];
#pragma unroll
        for (int nt = 0; nt < 2; nt++) {
            uint2 vb = *(const uint2*)&B1[(nw + nt * 8 + l4) * 128 + off];
            hmma(&aB[0][nt][0], a00.x, a01.x, a00.y, a01.y, vb.x, vb.y);
            hmma(&aB[1][nt][0], a10.x, a11.x, a10.y, a11.y, vb.x, vb.y);
        }
#pragma unroll
        for (int nt = 0; nt < 2; nt++) {
            uint2 vb = *(const uint2*)&B2[(nw + nt * 8 + l4) * 128 + off];
            hmma(&aA[0][nt][0], a00.x, a01.x, a00.y, a01.y, vb.x, vb.y);
            hmma(&aA[1][nt][0], a10.x, a11.x, a10.y, a11.y, vb.x, vb.y);
        }
    }
}
// Write-only gather into this k-half's buffer.
__device__ __forceinline__ void gather2(float (*gs)[33], float acc[2][2][4],
                                        int mrow, int nw, int l4, int lq) {
#pragma unroll
    for (int mb = 0; mb < 2; mb++)
#pragma unroll
        for (int nt = 0; nt < 2; nt++) {
            int c = nw + nt * 8 + 2 * lq;
            int r = mrow + mb * 16 + l4;
            gs[r][c]     = acc[mb][nt][0]; gs[r][c + 1]     = acc[mb][nt][1];
            gs[r + 8][c] = acc[mb][nt][2]; gs[r + 8][c + 1] = acc[mb][nt][3];
        }
}
// LSTM cell: register c-state, sums the two k-half gather buffers.
__device__ __forceinline__ void cell_regs(const float (*g0)[33], const float (*g1)[33],
                                          const float* bs, float rc[2],
                                          __half* dst, __half* hist, int d0, int tid) {
    int ch = d0 >> 7, dl = d0 & 127;
#pragma unroll
    for (int s = 0; s < 2; s++) {
        int idx = tid * 2 + s, r = idx >> 3, j = idx & 7;
        float gi = g0[r][j]      + g1[r][j]      + bs[j];
        float gf = g0[r][8 + j]  + g1[r][8 + j]  + bs[8 + j];
        float gg = g0[r][16 + j] + g1[r][16 + j] + bs[16 + j];
        float go = g0[r][24 + j] + g1[r][24 + j] + bs[24 + j];
        float c = sigm(gf) * rc[s] + sigm(gi) * ftanh(gg);
        rc[s] = c;
        __half h = __float2half_rn(sigm(go) * ftanh(c));
        long off = (long)ch * 8192 + r * 128 + img_off(r, dl + j);
        dst[off] = h;
        if (hist) hist[off] = h;
    }
}

// ---------------- init / pack kernels (R13 verbatim) ----------------
__global__ void init_kernel(const float* __restrict__ z) {
    int i = blockIdx.x * blockDim.x + threadIdx.x;
    int b = i >> 10, k = i & 1023;
    int idx = (k >> 7) * 8192 + b * 128 + img_off(b, k & 127);
    __half v = __float2half_rn(z[i]);
    g_h0p[0][idx] = v;
    g_h1p[0][idx] = v;
    if (i < 256) g_cnt[i] = 0u;
}
__global__ void pack_w(const float* __restrict__ src, __half* __restrict__ dst, int K) {
    int nch = K >> 7;
    long total = (long)NCTA * 32 * K;
    for (long i = blockIdx.x * (long)blockDim.x + threadIdx.x; i < total;
         i += (long)gridDim.x * blockDim.x) {
        int k = (int)(i % K);
        long j = i / K;
        int c = (int)(j & 31);
        int blk = (int)(j >> 5);
        int row = ((c >> 3) << 10) + (blk << 3) + (c & 7);
        long di = ((long)(blk * nch + (k >> 7)) * 32 + c) * 128 + img_off(c, k & 127);
        dst[di] = __float2half_rn(src[(long)row * K + k]);
    }
}
__global__ void pack_wl(const float* __restrict__ src, __half* __restrict__ dst) {
    long total = (long)8 * 32 * HH;
    for (long i = blockIdx.x * (long)blockDim.x + threadIdx.x; i < total;
         i += (long)gridDim.x * blockDim.x) {
        int k = (int)(i % HH);
        long j = i / HH;
        int c = (int)(j & 31);
        int blk = (int)(j >> 5);
        long di = ((long)(blk * 8 + (k >> 7)) * 32 + c) * 128 + img_off(c, k & 127);
        dst[di] = __float2half_rn(src[(long)(blk * 32 + c) * HH + k]);
    }
}
__global__ void pack_x(const float* __restrict__ x) {
    long total = (long)TT * BB * IND;
    for (long i = blockIdx.x * (long)blockDim.x + threadIdx.x; i < total;
         i += (long)gridDim.x * blockDim.x) {
        int k = (int)(i % IND);
        int b = (int)((i / IND) & 63);
        int t = (int)(i / (IND * 64));
        long di = (long)t * 16384 + (k >> 7) * 8192 + b * 128 + img_off(b, k & 127);
        g_xp[di] = __float2half_rn(x[((long)b * TT + t) * IND + k]);
    }
}

// ---------------- main persistent kernel ----------------
__global__ __launch_bounds__(256) void lstm_persist(
    const float* __restrict__ bih0, const float* __restrict__ bhh0,
    const float* __restrict__ bih1, const float* __restrict__ bhh1)
{
    extern __shared__ __align__(16) unsigned char smraw[];
    __half* SMh = (__half*)smraw;
    uint32_t sbase = smem_u32(smraw);
    uint32_t mb = sbase + MBOFF2;
    float (*gB0)[33] = (float(*)[33])(smraw + GOFF);
    float (*gB1)[33] = (float(*)[33])(smraw + GOFF + 8448);
    float (*gA0)[33] = (float(*)[33])(smraw + GOFF + 16896);
    float (*gA1)[33] = (float(*)[33])(smraw + GOFF + 25344);
    float* bs1 = (float*)(smraw + BIASOFF);
    float* bs0 = bs1 + 32;

    int tid = threadIdx.x, lane = tid & 31, w = tid >> 5;
    int ks = w >> 2;
    int mrow = ((w >> 1) & 1) * 32, nw = (w & 1) * 16;
    int l4 = lane >> 2, lq = lane & 3;
    int blk = blockIdx.x, d0 = blk * 8;

    const __half* W0h = g_W0h + (long)blk * 8 * 4096;
    const __half* W0x = g_W0x + (long)blk * 2 * 4096;
    const __half* W1i = g_W1i + (long)blk * 8 * 4096;
    const __half* W1h = g_W1h + (long)blk * 8 * 4096;

    if (tid == 0)
        for (int s = 0; s < 3; s++) { MB_INIT(mb + s * 8, 1); MB_INIT(mb + 24 + s * 8, 8); }
    if (tid < 32) {
        int g = tid >> 3, j = tid & 7, n = (g << 10) + d0 + j;
        bs0[tid] = bih0[n] + bhh0[n];
        bs1[tid] = bih1[n] + bhh1[n];
    }
    __syncthreads();

    long gC = 0, gP = 0;                 // consumed / produced chunk counters
    float rc0[2] = {0.f, 0.f}, rc1[2] = {0.f, 0.f};
    float (*gKA)[33] = ks ? gA1 : gA0;
    float (*gKB)[33] = ks ? gB1 : gB0;

    // ---- Prologue: A(0) = z @ W0h (4 superchunks), then x(0) prefetch ----
    {
        float accA[2][2][4] = {};
        const __half* A0 = g_h0p[0];
        if (tid == 0)
            for (int p = 0; p <= 2; p++, gP++)
                produce_g(sbase, gP, A0 + p * 16384, W0h + p * 8192, (const __half*)0);
        for (int i = 0; i < 4; i++, gC++) {
            if (tid == 0 && i >= 1 && i + 2 < 4) {
                produce_g(sbase, gP, A0 + (i + 2) * 16384, W0h + (i + 2) * 8192, (const __half*)0);
                gP++;
            }
            int s = (int)(gC % 3);
            mb_wait(mb + s * 8, (unsigned)((gC / 3) & 1));
            const __half* S = SMh + (long)s * 32768;
            mma_ks1(S + ks * 8192, S + 16384 + ks * 4096, accA, mrow, nw, l4, lq);
            if (lane == 0) MB_ARRIVE(mb + 24 + s * 8);
        }
        if (tid == 0) {                  // prefetch x(0) chunk (phase 0, local 0)
            produce_g(sbase, gP, g_xp, W0x, (const __half*)0);
            gP++;
        }
        gather2(gKA, accA, mrow, nw, l4, lq);
        __syncthreads();
        cell_regs(gA0, gA1, bs0, rc0, g_h0p[1], (__half*)0, d0, tid);
        grid_bar(NCTA);
    }

    // ---- Main loop: phase t = { B(t), A(t+1) }, one barrier per step ----
    for (int t = 0; t < TT; t++) {
        bool doA = (t + 1 < TT);
        const __half* h0new = g_h0p[(t + 1) & 1];
        const __half* h1old = g_h1p[t & 1];
        int NCH = doA ? 9 : 8;
        int dsh = doA ? 1 : 0;           // dual/h0 chunks start at this local index

        float accA[2][2][4] = {}, accB[2][2][4] = {};

        if (tid == 0) {
            for (int p = dsh; p <= 2; p++, gP++) {
                int q = p - dsh;
                produce_g(sbase, gP, h0new + q * 16384, W1i + q * 8192,
                          doA ? (W0h + q * 8192) : (const __half*)0);
            }
        }
        for (int i = 0; i < NCH; i++, gC++) {
            if (tid == 0 && i >= 1 && i + 2 < NCH) {
                int p = i + 2;
                const __half *A, *B1, *B2 = (const __half*)0;
                int q = p - dsh;
                if (q < 4) {
                    A = h0new + q * 16384; B1 = W1i + q * 8192;
                    if (doA) B2 = W0h + q * 8192;
                } else {
                    A = h1old + (q - 4) * 16384; B1 = W1h + (q - 4) * 8192;
                }
                produce_g(sbase, gP, A, B1, B2);
                gP++;
            }
            int s = (int)(gC % 3);
            mb_wait(mb + s * 8, (unsigned)((gC / 3) & 1));
            const __half* S   = SMh + (long)s * 32768;
            const __half* Ak  = S + ks * 8192;
            const __half* B1k = S + 16384 + ks * 4096;
            const __half* B2k = S + 24576 + ks * 4096;
            int q = i - dsh;
            if (doA && i == 0)       mma_ks1(Ak, B1k, accA, mrow, nw, l4, lq);       // x chunk
            else if (q < 4) {
                if (doA) mma_ks2(Ak, B1k, B2k, accB, accA, mrow, nw, l4, lq);
                else     mma_ks1(Ak, B1k, accB, mrow, nw, l4, lq);
            } else                    mma_ks1(Ak, B1k, accB, mrow, nw, l4, lq);
            if (lane == 0) MB_ARRIVE(mb + 24 + s * 8);
        }
        if (tid == 0 && t < TT - 2) {    // prefetch next phase's x chunk
            produce_g(sbase, gP, g_xp + (long)(t + 1) * 16384, W0x, (const __half*)0);
            gP++;
        }

        gather2(gKB, accB, mrow, nw, l4, lq);
        if (doA) gather2(gKA, accA, mrow, nw, l4, lq);
        __syncthreads();
        cell_regs(gB0, gB1, bs1, rc1, g_h1p[(t + 1) & 1],
                  g_h1all + (long)t * 65536, d0, tid);
        if (doA) {
            cell_regs(gA0, gA1, bs0, rc0, g_h0p[t & 1], (__half*)0, d0, tid);
            grid_bar((unsigned)(t + 2) * NCTA);
        }
    }
}

// ---------------- deferred output projection (R13 discipline) ----------------
__global__ __launch_bounds__(256) void out_kernel(
    const float* __restrict__ blin, float* __restrict__ out)
{
    extern __shared__ __align__(16) unsigned char smraw[];
    __half* SMh = (__half*)smraw;
    uint32_t sbase = smem_u32(smraw);
    uint32_t mb = sbase + MBOFF2;
    float (*g0)[33] = (float(*)[33])(smraw + GOFF);
    float (*g1)[33] = (float(*)[33])(smraw + GOFF + 8448);

    int tid = threadIdx.x, lane = tid & 31, w = tid >> 5;
    int ks = w >> 2;
    int mrow = ((w >> 1) & 1) * 32, nw = (w & 1) * 16;
    int l4 = lane >> 2, lq = lane & 3;
    int t = blockIdx.x, cb = blockIdx.y;

    const __half* A  = g_h1all + (long)t * 65536;
    const __half* Wb = g_Wlp + (long)cb * 8 * 4096;
    float acc[2][2][4] = {};

    if (tid == 0)
        for (int s = 0; s < 3; s++) MB_INIT(mb + s * 8, 1);
    __syncthreads();

    if (tid == 0) {
        produce_o(sbase, 0, A, Wb);
        produce_o(sbase, 1, A + 16384, Wb + 8192);
    }
    for (int i = 0; i < 4; i++) {
        if (tid == 0 && i + 2 < 4)
            produce_o(sbase, i + 2, A + (i + 2) * 16384, Wb + (i + 2) * 8192);
        int s = i % 3;
        mb_wait(mb + s * 8, (unsigned)((i / 3) & 1));
        const __half* S = SMh + (long)s * 32768;
        mma_ks1(S + ks * 8192, S + 16384 + ks * 4096, acc, mrow, nw, l4, lq);
        __syncthreads();
    }

    gather2(ks ? g1 : g0, acc, mrow, nw, l4, lq);
    __syncthreads();

#pragma unroll
    for (int s = 0; s < 8; s++) {
        int idx = tid + s * 256;
        int b = idx >> 5, c = idx & 31;
        int o = cb * 32 + c;
        out[(long)b * (TT * OUTD) + t * OUTD + o] = g0[b][c] + g1[b][c] + blin[o];
    }
}

// ---------------- host launcher ----------------
extern "C" void kernel_launch(void* const* d_in, const int* in_sizes, int n_in,
                              void* d_out, int out_size)
{
    const float* z    = (const float*)d_in[0];
    const float* x    = (const float*)d_in[1];
    const float* Wih0 = (const float*)d_in[2];
    const float* Whh0 = (const float*)d_in[3];
    const float* bih0 = (const float*)d_in[4];
    const float* bhh0 = (const float*)d_in[5];
    const float* Wih1 = (const float*)d_in[6];
    const float* Whh1 = (const float*)d_in[7];
    const float* bih1 = (const float*)d_in[8];
    const float* bhh1 = (const float*)d_in[9];
    const float* Wlin = (const float*)d_in[10];
    const float* blin = (const float*)d_in[11];
    float* out = (float*)d_out;

    cudaFuncSetAttribute(lstm_persist, cudaFuncAttributeMaxDynamicSharedMemorySize, SMEM_TOT);
    cudaFuncSetAttribute(out_kernel,   cudaFuncAttributeMaxDynamicSharedMemorySize, SMEM_TOT);

    __half* dW0h; cudaGetSymbolAddress((void**)&dW0h, g_W0h);
    __half* dW0x; cudaGetSymbolAddress((void**)&dW0x, g_W0x);
    __half* dW1i; cudaGetSymbolAddress((void**)&dW1i, g_W1i);
    __half* dW1h; cudaGetSymbolAddress((void**)&dW1h, g_W1h);
    __half* dWlp; cudaGetSymbolAddress((void**)&dWlp, g_Wlp);

    init_kernel<<<64, 1024>>>(z);
    pack_w<<<2048, 256>>>(Whh0, dW0h, HH);
    pack_w<<<1024, 256>>>(Wih0, dW0x, IND);
    pack_w<<<2048, 256>>>(Wih1, dW1i, HH);
    pack_w<<<2048, 256>>>(Whh1, dW1h, HH);
    pack_wl<<<256, 256>>>(Wlin, dWlp);
    pack_x<<<2048, 256>>>(x);

    lstm_persist<<<NCTA, 256, SMEM_TOT>>>(bih0, bhh0, bih1, bhh1);
    out_kernel<<<dim3(TT, OUTD / 32), 256, SMEM_TOT>>>(blin, out);
}

// round 15
// speedup vs baseline: 1.9340x; 1.1251x over previous
#include <cuda_runtime.h>
#include <cuda_fp16.h>
#include <stdint.h>
#include <math.h>

#define BB   64
#define TT   512
#define IND  256
#define OUTD 256
#define HH   1024
#define NCTA 128
#define NTHR 288                     // 8 compute warps + 1 producer warp
#define STGB   65536                 // stage: A 32KB | B1 16KB | B2 16KB
#define GOFF   (3 * STGB)            // gather buffers
#define MBOFF2 (GOFF + 4 * 8448)     // full[3]@0,8,16  cons[3]@24,32,40
#define BIASOFF (MBOFF2 + 64)
#define SMEM_TOT (BIASOFF + 256)

// ---------------- persistent device state (chunk-image layouts) ----------------
__device__ __half   g_h0p[2][8 * 8192];
__device__ __half   g_h1p[2][8 * 8192];
__device__ __half   g_h1all[(long)TT * 8 * 8192];
__device__ __half   g_xp[(long)TT * 2 * 8192];
__device__ __half   g_W0h[NCTA * 8 * 4096];
__device__ __half   g_W0x[NCTA * 2 * 4096];
__device__ __half   g_W1i[NCTA * 8 * 4096];
__device__ __half   g_W1h[NCTA * 8 * 4096];
__device__ __half   g_Wlp[8 * 8 * 4096];
__device__ unsigned g_cnt[256];

// ---------------- helpers ----------------
__device__ __forceinline__ float sigm(float v) {
    return __fdividef(1.f, 1.f + __expf(-v));
}
__device__ __forceinline__ float ftanh(float x) {
    float e = __expf(-2.f * x);
    return __fdividef(1.f - e, 1.f + e);
}
__device__ __forceinline__ int kpos16(int k) {
    int q = k >> 1, b = k & 1;
    return ((q & 3) << 2) | ((q >> 2) << 1) | b;
}
__device__ __forceinline__ int img_off(int row, int kloc) {
    int kpl = (kloc & ~15) + kpos16(kloc & 15);
    return kpl ^ ((row & 7) << 4);
}
__device__ __forceinline__ uint32_t smem_u32(const void* p) {
    uint32_t a;
    asm("{ .reg .u64 t; cvta.to.shared.u64 t, %1; cvt.u32.u64 %0, t; }" : "=r"(a) : "l"(p));
    return a;
}
#define MB_INIT(a, c)  asm volatile("mbarrier.init.shared.b64 [%0], %1;" :: "r"(a), "r"(c) : "memory")
#define MB_EXPECT(a,b) asm volatile("mbarrier.arrive.expect_tx.shared.b64 _, [%0], %1;" :: "r"(a), "r"(b) : "memory")
#define MB_ARRIVE(a)   asm volatile("mbarrier.arrive.shared.b64 _, [%0];" :: "r"(a) : "memory")
__device__ __forceinline__ void mb_wait(uint32_t m, unsigned p) {
    asm volatile(
        "{\n\t.reg .pred P1;\n\tLW_%=:\n\t"
        "mbarrier.try_wait.parity.acquire.cta.shared::cta.b64 P1, [%0], %1, 0x989680;\n\t"
        "@P1 bra.uni LD_%=;\n\tbra.uni LW_%=;\n\tLD_%=:\n\t}" :: "r"(m), "r"(p) : "memory");
}
__device__ __forceinline__ void bulk_cp(uint32_t d, const void* s, unsigned b, uint32_t m) {
    asm volatile("cp.async.bulk.shared::cluster.global.mbarrier::complete_tx::bytes [%0], [%1], %2, [%3];"
                 :: "r"(d), "l"(s), "r"(b), "r"(m) : "memory");
}
// producer with consumed-backpressure
__device__ __forceinline__ void produce_g(uint32_t sb, long g, const __half* A,
                                          const __half* B1, const __half* B2) {
    int s = (int)(g % 3);
    uint32_t mb = sb + MBOFF2;
    if (g >= 3) mb_wait(mb + 24 + s * 8, (unsigned)(((g / 3) - 1) & 1));
    uint32_t st = sb + s * STGB, fb = mb + s * 8;
    MB_EXPECT(fb, B2 ? 65536u : 49152u);
    bulk_cp(st, A, 32768u, fb);
    bulk_cp(st + 32768, B1, 16384u, fb);
    if (B2) bulk_cp(st + 49152, B2, 16384u, fb);
}
__device__ __forceinline__ void produce_o(uint32_t sb, long g, const __half* A, const __half* B1) {
    int s = (int)(g % 3);
    uint32_t st = sb + s * STGB, fb = sb + MBOFF2 + s * 8;
    MB_EXPECT(fb, 49152u);
    bulk_cp(st, A, 32768u, fb);
    bulk_cp(st + 32768, B1, 16384u, fb);
}
__device__ __forceinline__ unsigned ld_acq(const unsigned* p) {
    unsigned v;
    asm volatile("ld.acquire.gpu.global.u32 %0, [%1];" : "=r"(v) : "l"(p) : "memory");
    return v;
}
__device__ __forceinline__ void grid_bar(unsigned target) {
    __syncthreads();
    if (threadIdx.x == 0) {
        __threadfence();
        atomicAdd(&g_cnt[(blockIdx.x & 7) << 5], 1u);
        unsigned s;
        do { s = 0;
#pragma unroll
            for (int i = 0; i < 8; i++) s += ld_acq(&g_cnt[i << 5]);
        } while (s < target);
    }
    __syncthreads();
}
__device__ __forceinline__ void hmma(float* c, uint32_t a0, uint32_t a1, uint32_t a2,
                                     uint32_t a3, uint32_t b0, uint32_t b1) {
    asm volatile(
        "mma.sync.aligned.m16n8k16.row.col.f32.f16.f16.f32 "
        "{%0,%1,%2,%3}, {%4,%5,%6,%7}, {%8,%9}, {%0,%1,%2,%3};"
        : "+f"(c[0]), "+f"(c[1]), "+f"(c[2]), "+f"(c[3])
        : "r"(a0), "r"(a1), "r"(a2), "r"(a3), "r"(b0), "r"(b1));
}
__device__ __forceinline__ void mma_ks1(const __half* A, const __half* B,
                                        float acc[2][2][4], int mrow, int nw, int l4, int lq) {
#pragma unroll
    for (int g = 0; g < 8; g++) {
        int off = (g * 16 + 4 * lq) ^ (l4 << 4);
        uint2 a00 = *(const uint2*)&A[(mrow + l4) * 128 + off];
        uint2 a01 = *(const uint2*)&A[(mrow + 8 + l4) * 128 + off];
        uint2 a10 = *(const uint2*)&A[(mrow + 16 + l4) * 128 + off];
        uint2 a11 = *(const uint2*)&A[(mrow + 24 + l4) * 128 + off];
#pragma unroll
        for (int nt = 0; nt < 2; nt++) {
            uint2 vb = *(const uint2*)&B[(nw + nt * 8 + l4) * 128 + off];
            hmma(&acc[0][nt][0], a00.x, a01.x, a00.y, a01.y, vb.x, vb.y);
            hmma(&acc[1][nt][0], a10.x, a11.x, a10.y, a11.y, vb.x, vb.y);
        }
    }
}
__device__ __forceinline__ void mma_ks2(const __half* A, const __half* B1, const __half* B2,
                                        float aB[2][2][4], float aA[2][2][4],
                                        int mrow, int nw, int l4, int lq) {
#pragma unroll
    for (int g = 0; g < 8; g++) {
        int off = (g * 16 + 4 * lq) ^ (l4 << 4);
        uint2 a00 = *(const uint2*)&A[(mrow + l4) * 128 + off];
        uint2 a01 = *(const uint2*)&A[(mrow + 8 + l4) * 128 + off];
        uint2 a10 = *(const uint2*)&A[(mrow + 16 + l4) * 128 + off];
        uint2 a11 = *(const uint2*)&A[(mrow + 24 + l4) * 128 + off];
#pragma unroll
        for (int nt = 0; nt < 2; nt++) {
            uint2 vb = *(const uint2*)&B1[(nw + nt * 8 + l4) * 128 + off];
            hmma(&aB[0][nt][0], a00.x, a01.x, a00.y, a01.y, vb.x, vb.y);
            hmma(&aB[1][nt][0], a10.x, a11.x, a10.y, a11.y, vb.x, vb.y);
        }
#pragma unroll
        for (int nt = 0; nt < 2; nt++) {
            uint2 vb = *(const uint2*)&B2[(nw + nt * 8 + l4) * 128 + off];
            hmma(&aA[0][nt][0], a00.x, a01.x, a00.y, a01.y, vb.x, vb.y);
            hmma(&aA[1][nt][0], a10.x, a11.x, a10.y, a11.y, vb.x, vb.y);
        }
    }
}
__device__ __forceinline__ void gather2(float (*gs)[33], float acc[2][2][4],
                                        int mrow, int nw, int l4, int lq) {
#pragma unroll
    for (int mb = 0; mb < 2; mb++)
#pragma unroll
        for (int nt = 0; nt < 2; nt++) {
            int c = nw + nt * 8 + 2 * lq;
            int r = mrow + mb * 16 + l4;
            gs[r][c]     = acc[mb][nt][0]; gs[r][c + 1]     = acc[mb][nt][1];
            gs[r + 8][c] = acc[mb][nt][2]; gs[r + 8][c + 1] = acc[mb][nt][3];
        }
}
__device__ __forceinline__ void cell_regs(const float (*g0)[33], const float (*g1)[33],
                                          const float* bs, float rc[2],
                                          __half* dst, __half* hist, int d0, int tid) {
    int ch = d0 >> 7, dl = d0 & 127;
#pragma unroll
    for (int s = 0; s < 2; s++) {
        int idx = tid * 2 + s, r = idx >> 3, j = idx & 7;
        float gi = g0[r][j]      + g1[r][j]      + bs[j];
        float gf = g0[r][8 + j]  + g1[r][8 + j]  + bs[8 + j];
        float gg = g0[r][16 + j] + g1[r][16 + j] + bs[16 + j];
        float go = g0[r][24 + j] + g1[r][24 + j] + bs[24 + j];
        float c = sigm(gf) * rc[s] + sigm(gi) * ftanh(gg);
        rc[s] = c;
        __half h = __float2half_rn(sigm(go) * ftanh(c));
        long off = (long)ch * 8192 + r * 128 + img_off(r, dl + j);
        dst[off] = h;
        if (hist) hist[off] = h;
    }
}

// ---------------- init / pack kernels (merged: 4 launches before lstm) ----------------
__global__ void init_kernel(const float* __restrict__ z) {
    int i = blockIdx.x * blockDim.x + threadIdx.x;
    int b = i >> 10, k = i & 1023;
    int idx = (k >> 7) * 8192 + b * 128 + img_off(b, k & 127);
    __half v = __float2half_rn(z[i]);
    g_h0p[0][idx] = v;
    g_h1p[0][idx] = v;
    if (i < 256) g_cnt[i] = 0u;
}
__device__ __forceinline__ void pack_w_body(const float* src, __half* dst, int K, long i) {
    int nch = K >> 7;
    int k = (int)(i % K);
    long j = i / K;
    int c = (int)(j & 31);
    int blk = (int)(j >> 5);
    int row = ((c >> 3) << 10) + (blk << 3) + (c & 7);
    long di = ((long)(blk * nch + (k >> 7)) * 32 + c) * 128 + img_off(c, k & 127);
    dst[di] = __float2half_rn(src[(long)row * K + k]);
}
// packs two weight matrices in one launch
__global__ void pack_w2(const float* __restrict__ sA, __half* __restrict__ dA, int KA,
                        const float* __restrict__ sB, __half* __restrict__ dB, int KB_) {
    long tA = (long)NCTA * 32 * KA, tB = (long)NCTA * 32 * KB_;
    for (long i = blockIdx.x * (long)blockDim.x + threadIdx.x; i < tA + tB;
         i += (long)gridDim.x * blockDim.x) {
        if (i < tA) pack_w_body(sA, dA, KA, i);
        else        pack_w_body(sB, dB, KB_, i - tA);
    }
}
// packs Wlin + x in one launch
__global__ void pack_misc(const float* __restrict__ wl, const float* __restrict__ x) {
    long tW = 8L * 32 * HH;
    long tX = (long)TT * BB * IND;
    for (long i = blockIdx.x * (long)blockDim.x + threadIdx.x; i < tW + tX;
         i += (long)gridDim.x * blockDim.x) {
        if (i < tW) {
            int k = (int)(i % HH);
            long j = i / HH;
            int c = (int)(j & 31);
            int blk = (int)(j >> 5);
            long di = ((long)(blk * 8 + (k >> 7)) * 32 + c) * 128 + img_off(c, k & 127);
            g_Wlp[di] = __float2half_rn(wl[(long)(blk * 32 + c) * HH + k]);
        } else {
            long ii = i - tW;
            int k = (int)(ii % IND);
            int b = (int)((ii / IND) & 63);
            int t = (int)(ii / (IND * 64));
            long di = (long)t * 16384 + (k >> 7) * 8192 + b * 128 + img_off(b, k & 127);
            g_xp[di] = __float2half_rn(x[((long)b * TT + t) * IND + k]);
        }
    }
}

// ---------------- main persistent kernel (warp-specialized) ----------------
__global__ __launch_bounds__(NTHR) void lstm_persist(
    const float* __restrict__ bih0, const float* __restrict__ bhh0,
    const float* __restrict__ bih1, const float* __restrict__ bhh1)
{
    extern __shared__ __align__(16) unsigned char smraw[];
    __half* SMh = (__half*)smraw;
    uint32_t sbase = smem_u32(smraw);
    uint32_t mb = sbase + MBOFF2;
    float (*gB0)[33] = (float(*)[33])(smraw + GOFF);
    float (*gB1)[33] = (float(*)[33])(smraw + GOFF + 8448);
    float (*gA0)[33] = (float(*)[33])(smraw + GOFF + 16896);
    float (*gA1)[33] = (float(*)[33])(smraw + GOFF + 25344);
    float* bs1 = (float*)(smraw + BIASOFF);
    float* bs0 = bs1 + 32;

    int tid = threadIdx.x, lane = tid & 31, w = tid >> 5;
    bool comp = (tid < 256);
    bool prod = (tid == 256);
    int ks = w >> 2;
    int mrow = ((w >> 1) & 1) * 32, nw = (w & 1) * 16;
    int l4 = lane >> 2, lq = lane & 3;
    int blk = blockIdx.x, d0 = blk * 8;

    const __half* W0h = g_W0h + (long)blk * 8 * 4096;
    const __half* W0x = g_W0x + (long)blk * 2 * 4096;
    const __half* W1i = g_W1i + (long)blk * 8 * 4096;
    const __half* W1h = g_W1h + (long)blk * 8 * 4096;

    if (tid == 0)
        for (int s = 0; s < 3; s++) { MB_INIT(mb + s * 8, 1); MB_INIT(mb + 24 + s * 8, 8); }
    if (tid < 32) {
        int g = tid >> 3, j = tid & 7, n = (g << 10) + d0 + j;
        bs0[tid] = bih0[n] + bhh0[n];
        bs1[tid] = bih1[n] + bhh1[n];
    }
    __syncthreads();

    long gC = 0, gP = 0;
    float rc0[2] = {0.f, 0.f}, rc1[2] = {0.f, 0.f};
    float (*gKA)[33] = ks ? gA1 : gA0;
    float (*gKB)[33] = ks ? gB1 : gB0;

    // ---- Prologue: A(0) = z @ W0h, then x(0) prefetch ----
    {
        if (prod) {
            const __half* A0 = g_h0p[0];
            for (int q = 0; q < 4; q++, gP++)
                produce_g(sbase, gP, A0 + q * 16384, W0h + q * 8192, (const __half*)0);
            produce_g(sbase, gP, g_xp, W0x, (const __half*)0);
            gP++;
        }
        if (comp) {
            float accA[2][2][4] = {};
            for (int i = 0; i < 4; i++, gC++) {
                int s = (int)(gC % 3);
                mb_wait(mb + s * 8, (unsigned)((gC / 3) & 1));
                const __half* S = SMh + (long)s * 32768;
                mma_ks1(S + ks * 8192, S + 16384 + ks * 4096, accA, mrow, nw, l4, lq);
                if (lane == 0) MB_ARRIVE(mb + 24 + s * 8);
            }
            gather2(gKA, accA, mrow, nw, l4, lq);
        } else gC = 4;
        __syncthreads();
        if (comp) cell_regs(gA0, gA1, bs0, rc0, g_h0p[1], (__half*)0, d0, tid);
        grid_bar(NCTA);
    }

    // ---- Main loop: phase t = { B(t), A(t+1) }, one barrier per step ----
    for (int t = 0; t < TT; t++) {
        bool doA = (t + 1 < TT);
        const __half* h0new = g_h0p[(t + 1) & 1];
        const __half* h1old = g_h1p[t & 1];
        int NCH = doA ? 9 : 8;

        if (prod) {
            for (int q = 0; q < 4; q++, gP++)
                produce_g(sbase, gP, h0new + q * 16384, W1i + q * 8192,
                          doA ? (W0h + q * 8192) : (const __half*)0);
            for (int q = 0; q < 4; q++, gP++)
                produce_g(sbase, gP, h1old + q * 16384, W1h + q * 8192, (const __half*)0);
            if (t < TT - 2) {
                produce_g(sbase, gP, g_xp + (long)(t + 1) * 16384, W0x, (const __half*)0);
                gP++;
            }
        }
        if (comp) {
            float accA[2][2][4] = {}, accB[2][2][4] = {};
            int dsh = doA ? 1 : 0;
            for (int i = 0; i < NCH; i++, gC++) {
                int s = (int)(gC % 3);
                mb_wait(mb + s * 8, (unsigned)((gC / 3) & 1));
                const __half* S   = SMh + (long)s * 32768;
                const __half* Ak  = S + ks * 8192;
                const __half* B1k = S + 16384 + ks * 4096;
                const __half* B2k = S + 24576 + ks * 4096;
                int q = i - dsh;
                if (doA && i == 0)  mma_ks1(Ak, B1k, accA, mrow, nw, l4, lq);   // x chunk
                else if (q < 4) {
                    if (doA) mma_ks2(Ak, B1k, B2k, accB, accA, mrow, nw, l4, lq);
                    else     mma_ks1(Ak, B1k, accB, mrow, nw, l4, lq);
                } else              mma_ks1(Ak, B1k, accB, mrow, nw, l4, lq);
                if (lane == 0) MB_ARRIVE(mb + 24 + s * 8);
            }
            gather2(gKB, accB, mrow, nw, l4, lq);
            if (doA) gather2(gKA, accA, mrow, nw, l4, lq);
        } else gC += NCH;
        __syncthreads();
        if (comp) {
            cell_regs(gB0, gB1, bs1, rc1, g_h1p[(t + 1) & 1],
                      g_h1all + (long)t * 65536, d0, tid);
            if (doA) cell_regs(gA0, gA1, bs0, rc0, g_h0p[t & 1], (__half*)0, d0, tid);
        }
        if (doA) grid_bar((unsigned)(t + 2) * NCTA);
    }
}

// ---------------- deferred output projection ----------------
__global__ __launch_bounds__(256) void out_kernel(
    const float* __restrict__ blin, float* __restrict__ out)
{
    extern __shared__ __align__(16) unsigned char smraw[];
    __half* SMh = (__half*)smraw;
    uint32_t sbase = smem_u32(smraw);
    uint32_t mb = sbase + MBOFF2;
    float (*g0)[33] = (float(*)[33])(smraw + GOFF);
    float (*g1)[33] = (float(*)[33])(smraw + GOFF + 8448);

    int tid = threadIdx.x, lane = tid & 31, w = tid >> 5;
    int ks = w >> 2;
    int mrow = ((w >> 1) & 1) * 32, nw = (w & 1) * 16;
    int l4 = lane >> 2, lq = lane & 3;
    int t = blockIdx.x, cb = blockIdx.y;

    const __half* A  = g_h1all + (long)t * 65536;
    const __half* Wb = g_Wlp + (long)cb * 8 * 4096;
    float acc[2][2][4] = {};

    if (tid == 0)
        for (int s = 0; s < 3; s++) MB_INIT(mb + s * 8, 1);
    __syncthreads();

    if (tid == 0) {
        produce_o(sbase, 0, A, Wb);
        produce_o(sbase, 1, A + 16384, Wb + 8192);
    }
    for (int i = 0; i < 4; i++) {
        if (tid == 0 && i + 2 < 4)
            produce_o(sbase, i + 2, A + (i + 2) * 16384, Wb + (i + 2) * 8192);
        int s = i % 3;
        mb_wait(mb + s * 8, (unsigned)((i / 3) & 1));
        const __half* S = SMh + (long)s * 32768;
        mma_ks1(S + ks * 8192, S + 16384 + ks * 4096, acc, mrow, nw, l4, lq);
        __syncthreads();
    }

    gather2(ks ? g1 : g0, acc, mrow, nw, l4, lq);
    __syncthreads();

#pragma unroll
    for (int s = 0; s < 8; s++) {
        int idx = tid + s * 256;
        int b = idx >> 5, c = idx & 31;
        int o = cb * 32 + c;
        out[(long)b * (TT * OUTD) + t * OUTD + o] = g0[b][c] + g1[b][c] + blin[o];
    }
}

// ---------------- host launcher ----------------
extern "C" void kernel_launch(void* const* d_in, const int* in_sizes, int n_in,
                              void* d_out, int out_size)
{
    const float* z    = (const float*)d_in[0];
    const float* x    = (const float*)d_in[1];
    const float* Wih0 = (const float*)d_in[2];
    const float* Whh0 = (const float*)d_in[3];
    const float* bih0 = (const float*)d_in[4];
    const float* bhh0 = (const float*)d_in[5];
    const float* Wih1 = (const float*)d_in[6];
    const float* Whh1 = (const float*)d_in[7];
    const float* bih1 = (const float*)d_in[8];
    const float* bhh1 = (const float*)d_in[9];
    const float* Wlin = (const float*)d_in[10];
    const float* blin = (const float*)d_in[11];
    float* out = (float*)d_out;

    cudaFuncSetAttribute(lstm_persist, cudaFuncAttributeMaxDynamicSharedMemorySize, SMEM_TOT);
    cudaFuncSetAttribute(out_kernel,   cudaFuncAttributeMaxDynamicSharedMemorySize, SMEM_TOT);

    __half* dW0h; cudaGetSymbolAddress((void**)&dW0h, g_W0h);
    __half* dW0x; cudaGetSymbolAddress((void**)&dW0x, g_W0x);
    __half* dW1i; cudaGetSymbolAddress((void**)&dW1i, g_W1i);
    __half* dW1h; cudaGetSymbolAddress((void**)&dW1h, g_W1h);

    // Launch order: init(0), pack_w2(1), pack_w2(2), pack_misc(3), lstm(4), out(5)
    init_kernel<<<64, 1024>>>(z);
    pack_w2<<<2048, 256>>>(Whh0, dW0h, HH, Wih1, dW1i, HH);
    pack_w2<<<2048, 256>>>(Whh1, dW1h, HH, Wih0, dW0x, IND);
    pack_misc<<<2048, 256>>>(Wlin, x);

    lstm_persist<<<NCTA, NTHR, SMEM_TOT>>>(bih0, bhh0, bih1, bhh1);
    out_kernel<<<dim3(TT, OUTD / 32), 256, SMEM_TOT>>>(blin, out);
}